// round 6
// baseline (speedup 1.0000x reference)
#include <cuda_runtime.h>
#include <math.h>

#define Nn 4096
#define Ff 64
#define LRALPHA 0.2f

// ---------- static device scratch (no allocation) ----------
__device__ unsigned g_adjbits[128 * Nn];      // [jword][node]
__device__ float  g_Wh[4 * Nn * Ff];
__device__ float  g_Wh2[Nn * Ff];
__device__ float4 g_rowdat[4 * Nn];           // (s1, e^s1, e^{.2 s1}, _)
__device__ float4 g_coldat[4 * Nn];
__device__ float  g_part[32 * Nn * Ff];       // split-K partials
__device__ float  g_den[32 * Nn];
__device__ float  g_hcat[Nn * 4 * Ff];
__device__ float  g_xres[Nn * Ff];
__device__ float  g_att2[Nn * Ff];

__device__ __forceinline__ unsigned long long fma2(unsigned long long a, unsigned long long b, unsigned long long c) {
    unsigned long long d; asm("fma.rn.f32x2 %0, %1, %2, %3;" : "=l"(d) : "l"(a), "l"(b), "l"(c)); return d;
}
__device__ __forceinline__ unsigned long long pack2(float x, float y) {
    unsigned long long d; asm("mov.b64 %0, {%1, %2};" : "=l"(d) : "f"(x), "f"(y)); return d;
}
__device__ __forceinline__ void unpack2(unsigned long long v, float& x, float& y) {
    asm("mov.b64 {%0, %1}, %2;" : "=f"(x), "=f"(y) : "l"(v));
}
__device__ __forceinline__ float eluf(float v) { return v > 0.f ? v : expm1f(v); }

// ---------- adj [N][N] int32 -> bitmask [128][N] ----------
__global__ void pack_adj(const int* __restrict__ adj) {
    int idx = blockIdx.x * 256 + threadIdx.x;
    int i = idx >> 12, j = idx & 4095;
    unsigned w = __ballot_sync(0xFFFFFFFFu, adj[idx] > 0);
    if ((j & 31) == 0) g_adjbits[(j >> 5) * Nn + i] = w;
}

// ---------- small GEMM: C = epi((A[+A2]) @ B + bias), 64x64 tiles ----------
__global__ __launch_bounds__(256)
void gemm64(const float* __restrict__ A, const float* __restrict__ A2,
            const float* __restrict__ B, const float* __restrict__ bias,
            float* __restrict__ C, int K, int transB, int doElu,
            long Bg, long Cg)
{
    __shared__ __align__(16) float As[16][68];
    __shared__ __align__(16) float Bs[16][68];
    B += (long)blockIdx.y * Bg;  C += (long)blockIdx.y * Cg;
    int tid = threadIdx.x, ibase = blockIdx.x * 64;
    int r0 = (tid >> 4) << 2, c0 = (tid & 15) << 2;
    int ai = tid >> 2, akq = tid & 3;
    float acc[4][4] = {};
    for (int k0 = 0; k0 < K; k0 += 16) {
        __syncthreads();
        float4 v = *(const float4*)&A[(size_t)(ibase + ai) * K + k0 + akq * 4];
        if (A2) { float4 u = *(const float4*)&A2[(size_t)(ibase + ai) * K + k0 + akq * 4];
                  v.x += u.x; v.y += u.y; v.z += u.z; v.w += u.w; }
        As[akq*4+0][ai] = v.x; As[akq*4+1][ai] = v.y; As[akq*4+2][ai] = v.z; As[akq*4+3][ai] = v.w;
        if (!transB) {
            int bk = tid >> 4, bf = (tid & 15) << 2;
            *(float4*)&Bs[bk][bf] = *(const float4*)&B[(size_t)(k0 + bk) * 64 + bf];
        } else {
            int bf = tid >> 2, bkq = tid & 3;
            float4 u = *(const float4*)&B[(size_t)bf * K + k0 + bkq * 4];
            Bs[bkq*4+0][bf] = u.x; Bs[bkq*4+1][bf] = u.y; Bs[bkq*4+2][bf] = u.z; Bs[bkq*4+3][bf] = u.w;
        }
        __syncthreads();
        #pragma unroll
        for (int k = 0; k < 16; ++k) {
            float4 a4 = *(const float4*)&As[k][r0];
            float4 b4 = *(const float4*)&Bs[k][c0];
            acc[0][0]+=a4.x*b4.x; acc[0][1]+=a4.x*b4.y; acc[0][2]+=a4.x*b4.z; acc[0][3]+=a4.x*b4.w;
            acc[1][0]+=a4.y*b4.x; acc[1][1]+=a4.y*b4.y; acc[1][2]+=a4.y*b4.z; acc[1][3]+=a4.y*b4.w;
            acc[2][0]+=a4.z*b4.x; acc[2][1]+=a4.z*b4.y; acc[2][2]+=a4.z*b4.z; acc[2][3]+=a4.z*b4.w;
            acc[3][0]+=a4.w*b4.x; acc[3][1]+=a4.w*b4.y; acc[3][2]+=a4.w*b4.z; acc[3][3]+=a4.w*b4.w;
        }
    }
    float b0 = bias?bias[c0]:0.f, b1 = bias?bias[c0+1]:0.f, b2 = bias?bias[c0+2]:0.f, b3 = bias?bias[c0+3]:0.f;
    #pragma unroll
    for (int r = 0; r < 4; ++r) {
        float4 o = make_float4(acc[r][0]+b0, acc[r][1]+b1, acc[r][2]+b2, acc[r][3]+b3);
        if (doElu) { o.x=eluf(o.x); o.y=eluf(o.y); o.z=eluf(o.z); o.w=eluf(o.w); }
        *(float4*)&C[(size_t)(ibase + r0 + r) * 64 + c0] = o;
    }
}

// ---------- per-node score scalars + exps ----------
__global__ void rowcol(const float* __restrict__ Wh, const float* __restrict__ a,
                       float4* __restrict__ rowdat, float4* __restrict__ coldat)
{
    __shared__ float as[128];
    int g = blockIdx.y;
    if (threadIdx.x < 128) as[threadIdx.x] = a[g * 128 + threadIdx.x];
    __syncthreads();
    int i = blockIdx.x * 256 + threadIdx.x;
    const float* w = Wh + ((size_t)g * Nn + i) * Ff;
    float s1 = 0.f, s2 = 0.f;
    #pragma unroll
    for (int f = 0; f < Ff; f += 4) {
        float4 v = *(const float4*)&w[f];
        s1 += v.x*as[f] + v.y*as[f+1] + v.z*as[f+2] + v.w*as[f+3];
        s2 += v.x*as[64+f] + v.y*as[64+f+1] + v.z*as[64+f+2] + v.w*as[64+f+3];
    }
    rowdat[g*Nn+i] = make_float4(s1, expf(s1), expf(LRALPHA*s1), 0.f);
    coldat[g*Nn+i] = make_float4(s2, expf(s2), expf(LRALPHA*s2), 0.f);
}

// ---------- masked-softmax aggregation: split-K partials, persistent grid ----------
__global__ __launch_bounds__(256)
void gat_attn(const float* __restrict__ Wh, const float4* __restrict__ rowdat,
              const float4* __restrict__ coldat, float* __restrict__ part,
              float* __restrict__ den, int G, int ksplit)
{
    const int TI = 128, TJ = 32;
    __shared__ __align__(16) float As[TJ][TI];
    __shared__ __align__(16) float Bs[TJ][Ff];
    __shared__ float4 cds[TJ];
    __shared__ unsigned bits[TI];
    __shared__ float dpart[256];

    int tid = threadIdx.x;
    int ft = tid & 7, it = tid >> 3;       // 8-feat x 4-row register tile
    int bi = tid & 127, jhalf = tid >> 7;  // A-build mapping
    int jchunk = Nn / ksplit, ntiles = jchunk / TJ;
    int nItems = 32 * G * ksplit;

    for (int item = blockIdx.x; item < nItems; item += gridDim.x) {
        int ib = item & 31, rest = item >> 5;
        int g = rest % G, ks = rest / G;
        int ibase = ib * TI, jbase0 = ks * jchunk;
        const float* WhG = Wh + (size_t)g * Nn * Ff;
        float4 rd = rowdat[g * Nn + ibase + bi];

        unsigned long long acc[4][4];
        unsigned long long z = pack2(0.f, 0.f);
        #pragma unroll
        for (int r = 0; r < 4; ++r) { acc[r][0]=z; acc[r][1]=z; acc[r][2]=z; acc[r][3]=z; }
        float dreg = 0.f;

        for (int t = 0; t < ntiles; ++t) {
            int jbase = jbase0 + t * TJ;
            __syncthreads();
            {   // Wh tile: 2048 floats flat
                const float4* src = (const float4*)(WhG + (size_t)jbase * Ff);
                float4* dst4 = (float4*)&Bs[0][0];
                dst4[tid] = src[tid];
                dst4[tid + 256] = src[tid + 256];
            }
            if (tid < TI) bits[tid] = g_adjbits[(jbase >> 5) * Nn + ibase + tid];
            if (tid < TJ) cds[tid] = coldat[g * Nn + jbase + tid];
            __syncthreads();
            unsigned myw = bits[bi];
            #pragma unroll
            for (int jj = 0; jj < 16; ++jj) {
                int j = jhalf + (jj << 1);
                float4 cd = cds[j];
                float w = (rd.x + cd.x > 0.f) ? (rd.y * cd.y) : (rd.z * cd.z);
                w = ((myw >> j) & 1u) ? w : 0.f;
                As[j][bi] = w;
                dreg += w;
            }
            __syncthreads();
            #pragma unroll 4
            for (int j = 0; j < TJ; ++j) {
                float4 av = *(const float4*)&As[j][it << 2];
                ulonglong2 b01 = *(const ulonglong2*)&Bs[j][ft << 3];
                ulonglong2 b23 = *(const ulonglong2*)&Bs[j][(ft << 3) + 4];
                unsigned long long w0 = pack2(av.x, av.x);
                acc[0][0]=fma2(w0,b01.x,acc[0][0]); acc[0][1]=fma2(w0,b01.y,acc[0][1]);
                acc[0][2]=fma2(w0,b23.x,acc[0][2]); acc[0][3]=fma2(w0,b23.y,acc[0][3]);
                unsigned long long w1 = pack2(av.y, av.y);
                acc[1][0]=fma2(w1,b01.x,acc[1][0]); acc[1][1]=fma2(w1,b01.y,acc[1][1]);
                acc[1][2]=fma2(w1,b23.x,acc[1][2]); acc[1][3]=fma2(w1,b23.y,acc[1][3]);
                unsigned long long w2 = pack2(av.z, av.z);
                acc[2][0]=fma2(w2,b01.x,acc[2][0]); acc[2][1]=fma2(w2,b01.y,acc[2][1]);
                acc[2][2]=fma2(w2,b23.x,acc[2][2]); acc[2][3]=fma2(w2,b23.y,acc[2][3]);
                unsigned long long w3 = pack2(av.w, av.w);
                acc[3][0]=fma2(w3,b01.x,acc[3][0]); acc[3][1]=fma2(w3,b01.y,acc[3][1]);
                acc[3][2]=fma2(w3,b23.x,acc[3][2]); acc[3][3]=fma2(w3,b23.y,acc[3][3]);
            }
        }
        dpart[tid] = dreg;
        __syncthreads();
        int p = g * ksplit + ks;
        if (tid < TI) den[(size_t)p * Nn + ibase + tid] = dpart[tid] + dpart[tid + 128];
        float* dst = part + (size_t)p * Nn * Ff;
        #pragma unroll
        for (int r = 0; r < 4; ++r) {
            int row = ibase + (it << 2) + r;
            float o0,o1,o2,o3,o4,o5,o6,o7;
            unpack2(acc[r][0],o0,o1); unpack2(acc[r][1],o2,o3);
            unpack2(acc[r][2],o4,o5); unpack2(acc[r][3],o6,o7);
            float4* d4 = (float4*)&dst[(size_t)row * Ff + (ft << 3)];
            d4[0] = make_float4(o0,o1,o2,o3);
            d4[1] = make_float4(o4,o5,o6,o7);
        }
    }
}

// ---------- combine split-K partials: normalize + ELU ----------
__global__ void combine(const float* __restrict__ part, const float* __restrict__ den,
                        float* __restrict__ dst, int G, int ksplit, int dstStride)
{
    int idx = blockIdx.x * 256 + threadIdx.x;
    int f = idx & 63;
    int g = (idx >> 6) % G;
    int i = idx / (64 * G);
    float s = 0.f, d = 0.f;
    for (int ks = 0; ks < ksplit; ++ks) {
        int p = g * ksplit + ks;
        s += part[((size_t)p * Nn + i) * Ff + f];
        d += den[(size_t)p * Nn + i];
    }
    dst[(size_t)i * dstStride + g * 64 + f] = eluf(s / d);
}

extern "C" void kernel_launch(void* const* d_in, const int* in_sizes, int n_in,
                              void* d_out, int out_size)
{
    const float* x       = (const float*)d_in[0];
    const int*   adj     = (const int*)d_in[1];
    const float* w_heads = (const float*)d_in[2];
    const float* a_heads = (const float*)d_in[3];
    const float* w_out   = (const float*)d_in[4];
    const float* a_out   = (const float*)d_in[5];
    const float* lin_w   = (const float*)d_in[6];
    const float* lin_b   = (const float*)d_in[7];
    const float* outlin_w= (const float*)d_in[8];
    const float* outlin_b= (const float*)d_in[9];
    float* out = (float*)d_out;

    float *pWh, *pWh2, *pHcat, *pXres, *pAtt2, *pPart, *pDen;
    float4 *pRow, *pCol;
    cudaGetSymbolAddress((void**)&pWh,  g_Wh);
    cudaGetSymbolAddress((void**)&pWh2, g_Wh2);
    cudaGetSymbolAddress((void**)&pHcat,g_hcat);
    cudaGetSymbolAddress((void**)&pXres,g_xres);
    cudaGetSymbolAddress((void**)&pAtt2,g_att2);
    cudaGetSymbolAddress((void**)&pPart,g_part);
    cudaGetSymbolAddress((void**)&pDen, g_den);
    cudaGetSymbolAddress((void**)&pRow, g_rowdat);
    cudaGetSymbolAddress((void**)&pCol, g_coldat);

    pack_adj<<<(Nn * Nn) / 256, 256>>>(adj);
    // layer-1 Wh per head + residual linear
    gemm64<<<dim3(Nn/64, 4), 256>>>(x, nullptr, w_heads, nullptr, pWh, 128, 0, 0, 128L*64, (long)Nn*64);
    gemm64<<<dim3(Nn/64, 1), 256>>>(x, nullptr, lin_w, lin_b, pXres, 128, 1, 0, 0, 0);
    rowcol<<<dim3(Nn/256, 4), 256>>>(pWh, a_heads, pRow, pCol);
    gat_attn<<<148, 256>>>(pWh, pRow, pCol, pPart, pDen, 4, 8);
    combine<<<(Nn * 4 * 64) / 256, 256>>>(pPart, pDen, pHcat, 4, 8, 256);
    // layer 2
    gemm64<<<dim3(Nn/64, 1), 256>>>(pHcat, nullptr, w_out, nullptr, pWh2, 256, 0, 0, 0, 0);
    rowcol<<<dim3(Nn/256, 1), 256>>>(pWh2, a_out, pRow, pCol);
    gat_attn<<<148, 256>>>(pWh2, pRow, pCol, pPart, pDen, 1, 32);
    combine<<<(Nn * 64) / 256, 256>>>(pPart, pDen, pAtt2, 1, 32, 64);
    // final: elu((xres + att2) @ outlin_w^T + b)
    gemm64<<<dim3(Nn/64, 1), 256>>>(pXres, pAtt2, outlin_w, outlin_b, out, 64, 1, 1, 0, 0);
}

// round 7
// speedup vs baseline: 1.0071x; 1.0071x over previous
#include <cuda_runtime.h>
#include <math.h>

#define Nn 4096
#define Ff 64
#define LRALPHA 0.2f

// ---------- static device scratch (no allocation) ----------
__device__ unsigned g_adjbits[128 * Nn];      // [jword][node]
__device__ float  g_Wh[4 * Nn * Ff];
__device__ float  g_Wh2[Nn * Ff];
__device__ float4 g_rowdat[4 * Nn];           // (s1, e^s1, e^{.2 s1}, _)
__device__ float4 g_coldat[4 * Nn];
__device__ float  g_part[32 * Nn * Ff];       // split-K partials
__device__ float  g_den[32 * Nn];
__device__ float  g_hcat[Nn * 4 * Ff];
__device__ float  g_xres[Nn * Ff];
__device__ float  g_att2[Nn * Ff];

__device__ __forceinline__ unsigned long long fma2(unsigned long long a, unsigned long long b, unsigned long long c) {
    unsigned long long d; asm("fma.rn.f32x2 %0, %1, %2, %3;" : "=l"(d) : "l"(a), "l"(b), "l"(c)); return d;
}
__device__ __forceinline__ unsigned long long pack2(float x, float y) {
    unsigned long long d; asm("mov.b64 %0, {%1, %2};" : "=l"(d) : "f"(x), "f"(y)); return d;
}
__device__ __forceinline__ void unpack2(unsigned long long v, float& x, float& y) {
    asm("mov.b64 {%0, %1}, %2;" : "=f"(x), "=f"(y) : "l"(v));
}
__device__ __forceinline__ float eluf(float v) { return v > 0.f ? v : expm1f(v); }

// ---------- adj [N][N] int32 -> bitmask [128][N] ----------
__global__ void pack_adj(const int* __restrict__ adj) {
    int idx = blockIdx.x * 256 + threadIdx.x;
    int i = idx >> 12, j = idx & 4095;
    unsigned w = __ballot_sync(0xFFFFFFFFu, adj[idx] > 0);
    if ((j & 31) == 0) g_adjbits[(j >> 5) * Nn + i] = w;
}

// ---------- small GEMM: C = epi((A[+A2]) @ B + bias), 64x64 tiles ----------
__global__ __launch_bounds__(256)
void gemm64(const float* __restrict__ A, const float* __restrict__ A2,
            const float* __restrict__ B, const float* __restrict__ bias,
            float* __restrict__ C, int K, int transB, int doElu,
            long Bg, long Cg)
{
    __shared__ __align__(16) float As[16][68];
    __shared__ __align__(16) float Bs[16][68];
    B += (long)blockIdx.y * Bg;  C += (long)blockIdx.y * Cg;
    int tid = threadIdx.x, ibase = blockIdx.x * 64;
    int r0 = (tid >> 4) << 2, c0 = (tid & 15) << 2;
    int ai = tid >> 2, akq = tid & 3;
    float acc[4][4] = {};
    for (int k0 = 0; k0 < K; k0 += 16) {
        __syncthreads();
        float4 v = *(const float4*)&A[(size_t)(ibase + ai) * K + k0 + akq * 4];
        if (A2) { float4 u = *(const float4*)&A2[(size_t)(ibase + ai) * K + k0 + akq * 4];
                  v.x += u.x; v.y += u.y; v.z += u.z; v.w += u.w; }
        As[akq*4+0][ai] = v.x; As[akq*4+1][ai] = v.y; As[akq*4+2][ai] = v.z; As[akq*4+3][ai] = v.w;
        if (!transB) {
            int bk = tid >> 4, bf = (tid & 15) << 2;
            *(float4*)&Bs[bk][bf] = *(const float4*)&B[(size_t)(k0 + bk) * 64 + bf];
        } else {
            int bf = tid >> 2, bkq = tid & 3;
            float4 u = *(const float4*)&B[(size_t)bf * K + k0 + bkq * 4];
            Bs[bkq*4+0][bf] = u.x; Bs[bkq*4+1][bf] = u.y; Bs[bkq*4+2][bf] = u.z; Bs[bkq*4+3][bf] = u.w;
        }
        __syncthreads();
        #pragma unroll
        for (int k = 0; k < 16; ++k) {
            float4 a4 = *(const float4*)&As[k][r0];
            float4 b4 = *(const float4*)&Bs[k][c0];
            acc[0][0]+=a4.x*b4.x; acc[0][1]+=a4.x*b4.y; acc[0][2]+=a4.x*b4.z; acc[0][3]+=a4.x*b4.w;
            acc[1][0]+=a4.y*b4.x; acc[1][1]+=a4.y*b4.y; acc[1][2]+=a4.y*b4.z; acc[1][3]+=a4.y*b4.w;
            acc[2][0]+=a4.z*b4.x; acc[2][1]+=a4.z*b4.y; acc[2][2]+=a4.z*b4.z; acc[2][3]+=a4.z*b4.w;
            acc[3][0]+=a4.w*b4.x; acc[3][1]+=a4.w*b4.y; acc[3][2]+=a4.w*b4.z; acc[3][3]+=a4.w*b4.w;
        }
    }
    float b0 = bias?bias[c0]:0.f, b1 = bias?bias[c0+1]:0.f, b2 = bias?bias[c0+2]:0.f, b3 = bias?bias[c0+3]:0.f;
    #pragma unroll
    for (int r = 0; r < 4; ++r) {
        float4 o = make_float4(acc[r][0]+b0, acc[r][1]+b1, acc[r][2]+b2, acc[r][3]+b3);
        if (doElu) { o.x=eluf(o.x); o.y=eluf(o.y); o.z=eluf(o.z); o.w=eluf(o.w); }
        *(float4*)&C[(size_t)(ibase + r0 + r) * 64 + c0] = o;
    }
}

// ---------- per-node score scalars + exps ----------
__global__ void rowcol(const float* __restrict__ Wh, const float* __restrict__ a,
                       float4* __restrict__ rowdat, float4* __restrict__ coldat)
{
    __shared__ float as[128];
    int g = blockIdx.y;
    if (threadIdx.x < 128) as[threadIdx.x] = a[g * 128 + threadIdx.x];
    __syncthreads();
    int i = blockIdx.x * 256 + threadIdx.x;
    const float* w = Wh + ((size_t)g * Nn + i) * Ff;
    float s1 = 0.f, s2 = 0.f;
    #pragma unroll
    for (int f = 0; f < Ff; f += 4) {
        float4 v = *(const float4*)&w[f];
        s1 += v.x*as[f] + v.y*as[f+1] + v.z*as[f+2] + v.w*as[f+3];
        s2 += v.x*as[64+f] + v.y*as[64+f+1] + v.z*as[64+f+2] + v.w*as[64+f+3];
    }
    rowdat[g*Nn+i] = make_float4(s1, expf(s1), expf(LRALPHA*s1), 0.f);
    coldat[g*Nn+i] = make_float4(s2, expf(s2), expf(LRALPHA*s2), 0.f);
}

// ---------- masked-softmax aggregation: split-K partials, persistent grid ----------
__global__ __launch_bounds__(256)
void gat_attn(const float* __restrict__ Wh, const float4* __restrict__ rowdat,
              const float4* __restrict__ coldat, float* __restrict__ part,
              float* __restrict__ den, int G, int ksplit)
{
    const int TI = 128, TJ = 32;
    __shared__ __align__(16) float As[TJ][TI];
    __shared__ __align__(16) float Bs[TJ][Ff];
    __shared__ float4 cds[TJ];
    __shared__ unsigned bits[TI];
    __shared__ float dpart[256];

    int tid = threadIdx.x;
    int ft = tid & 7, it = tid >> 3;       // 8-feat x 4-row register tile
    int bi = tid & 127, jhalf = tid >> 7;  // A-build mapping
    int jchunk = Nn / ksplit, ntiles = jchunk / TJ;
    int nItems = 32 * G * ksplit;

    for (int item = blockIdx.x; item < nItems; item += gridDim.x) {
        int ib = item & 31, rest = item >> 5;
        int g = rest % G, ks = rest / G;
        int ibase = ib * TI, jbase0 = ks * jchunk;
        const float* WhG = Wh + (size_t)g * Nn * Ff;
        float4 rd = rowdat[g * Nn + ibase + bi];

        unsigned long long acc[4][4];
        unsigned long long z = pack2(0.f, 0.f);
        #pragma unroll
        for (int r = 0; r < 4; ++r) { acc[r][0]=z; acc[r][1]=z; acc[r][2]=z; acc[r][3]=z; }
        float dreg = 0.f;

        for (int t = 0; t < ntiles; ++t) {
            int jbase = jbase0 + t * TJ;
            __syncthreads();
            {   // Wh tile: 2048 floats flat
                const float4* src = (const float4*)(WhG + (size_t)jbase * Ff);
                float4* dst4 = (float4*)&Bs[0][0];
                dst4[tid] = src[tid];
                dst4[tid + 256] = src[tid + 256];
            }
            if (tid < TI) bits[tid] = g_adjbits[(jbase >> 5) * Nn + ibase + tid];
            if (tid < TJ) cds[tid] = coldat[g * Nn + jbase + tid];
            __syncthreads();
            unsigned myw = bits[bi];
            #pragma unroll
            for (int jj = 0; jj < 16; ++jj) {
                int j = jhalf + (jj << 1);
                float4 cd = cds[j];
                float w = (rd.x + cd.x > 0.f) ? (rd.y * cd.y) : (rd.z * cd.z);
                w = ((myw >> j) & 1u) ? w : 0.f;
                As[j][bi] = w;
                dreg += w;
            }
            __syncthreads();
            #pragma unroll 4
            for (int j = 0; j < TJ; ++j) {
                float4 av = *(const float4*)&As[j][it << 2];
                ulonglong2 b01 = *(const ulonglong2*)&Bs[j][ft << 3];
                ulonglong2 b23 = *(const ulonglong2*)&Bs[j][(ft << 3) + 4];
                unsigned long long w0 = pack2(av.x, av.x);
                acc[0][0]=fma2(w0,b01.x,acc[0][0]); acc[0][1]=fma2(w0,b01.y,acc[0][1]);
                acc[0][2]=fma2(w0,b23.x,acc[0][2]); acc[0][3]=fma2(w0,b23.y,acc[0][3]);
                unsigned long long w1 = pack2(av.y, av.y);
                acc[1][0]=fma2(w1,b01.x,acc[1][0]); acc[1][1]=fma2(w1,b01.y,acc[1][1]);
                acc[1][2]=fma2(w1,b23.x,acc[1][2]); acc[1][3]=fma2(w1,b23.y,acc[1][3]);
                unsigned long long w2 = pack2(av.z, av.z);
                acc[2][0]=fma2(w2,b01.x,acc[2][0]); acc[2][1]=fma2(w2,b01.y,acc[2][1]);
                acc[2][2]=fma2(w2,b23.x,acc[2][2]); acc[2][3]=fma2(w2,b23.y,acc[2][3]);
                unsigned long long w3 = pack2(av.w, av.w);
                acc[3][0]=fma2(w3,b01.x,acc[3][0]); acc[3][1]=fma2(w3,b01.y,acc[3][1]);
                acc[3][2]=fma2(w3,b23.x,acc[3][2]); acc[3][3]=fma2(w3,b23.y,acc[3][3]);
            }
        }
        dpart[tid] = dreg;
        __syncthreads();
        int p = g * ksplit + ks;
        if (tid < TI) den[(size_t)p * Nn + ibase + tid] = dpart[tid] + dpart[tid + 128];
        float* dst = part + (size_t)p * Nn * Ff;
        #pragma unroll
        for (int r = 0; r < 4; ++r) {
            int row = ibase + (it << 2) + r;
            float o0,o1,o2,o3,o4,o5,o6,o7;
            unpack2(acc[r][0],o0,o1); unpack2(acc[r][1],o2,o3);
            unpack2(acc[r][2],o4,o5); unpack2(acc[r][3],o6,o7);
            float4* d4 = (float4*)&dst[(size_t)row * Ff + (ft << 3)];
            d4[0] = make_float4(o0,o1,o2,o3);
            d4[1] = make_float4(o4,o5,o6,o7);
        }
    }
}

// ---------- combine split-K partials: normalize + ELU ----------
__global__ void combine(const float* __restrict__ part, const float* __restrict__ den,
                        float* __restrict__ dst, int G, int ksplit, int dstStride)
{
    int idx = blockIdx.x * 256 + threadIdx.x;
    int f = idx & 63;
    int g = (idx >> 6) % G;
    int i = idx / (64 * G);
    float s = 0.f, d = 0.f;
    for (int ks = 0; ks < ksplit; ++ks) {
        int p = g * ksplit + ks;
        s += part[((size_t)p * Nn + i) * Ff + f];
        d += den[(size_t)p * Nn + i];
    }
    dst[(size_t)i * dstStride + g * 64 + f] = eluf(s / d);
}

extern "C" void kernel_launch(void* const* d_in, const int* in_sizes, int n_in,
                              void* d_out, int out_size)
{
    const float* x       = (const float*)d_in[0];
    const int*   adj     = (const int*)d_in[1];
    const float* w_heads = (const float*)d_in[2];
    const float* a_heads = (const float*)d_in[3];
    const float* w_out   = (const float*)d_in[4];
    const float* a_out   = (const float*)d_in[5];
    const float* lin_w   = (const float*)d_in[6];
    const float* lin_b   = (const float*)d_in[7];
    const float* outlin_w= (const float*)d_in[8];
    const float* outlin_b= (const float*)d_in[9];
    float* out = (float*)d_out;

    float *pWh, *pWh2, *pHcat, *pXres, *pAtt2, *pPart, *pDen;
    float4 *pRow, *pCol;
    cudaGetSymbolAddress((void**)&pWh,  g_Wh);
    cudaGetSymbolAddress((void**)&pWh2, g_Wh2);
    cudaGetSymbolAddress((void**)&pHcat,g_hcat);
    cudaGetSymbolAddress((void**)&pXres,g_xres);
    cudaGetSymbolAddress((void**)&pAtt2,g_att2);
    cudaGetSymbolAddress((void**)&pPart,g_part);
    cudaGetSymbolAddress((void**)&pDen, g_den);
    cudaGetSymbolAddress((void**)&pRow, g_rowdat);
    cudaGetSymbolAddress((void**)&pCol, g_coldat);

    pack_adj<<<(Nn * Nn) / 256, 256>>>(adj);
    // layer-1 Wh per head + residual linear
    gemm64<<<dim3(Nn/64, 4), 256>>>(x, nullptr, w_heads, nullptr, pWh, 128, 0, 0, 128L*64, (long)Nn*64);
    gemm64<<<dim3(Nn/64, 1), 256>>>(x, nullptr, lin_w, lin_b, pXres, 128, 1, 0, 0, 0);
    rowcol<<<dim3(Nn/256, 4), 256>>>(pWh, a_heads, pRow, pCol);
    gat_attn<<<148, 256>>>(pWh, pRow, pCol, pPart, pDen, 4, 8);
    combine<<<(Nn * 4 * 64) / 256, 256>>>(pPart, pDen, pHcat, 4, 8, 256);
    // layer 2
    gemm64<<<dim3(Nn/64, 1), 256>>>(pHcat, nullptr, w_out, nullptr, pWh2, 256, 0, 0, 0, 0);
    rowcol<<<dim3(Nn/256, 1), 256>>>(pWh2, a_out, pRow, pCol);
    gat_attn<<<148, 256>>>(pWh2, pRow, pCol, pPart, pDen, 1, 32);
    combine<<<(Nn * 64) / 256, 256>>>(pPart, pDen, pAtt2, 1, 32, 64);
    // final: elu((xres + att2) @ outlin_w^T + b)
    gemm64<<<dim3(Nn/64, 1), 256>>>(pXres, pAtt2, outlin_w, outlin_b, out, 64, 1, 1, 0, 0);
}

// round 9
// speedup vs baseline: 2.3807x; 2.3640x over previous
#include <cuda_runtime.h>
#include <cstdint>
#include <math.h>

#define Nn 4096
#define LRALPHA 0.2f

__device__ unsigned g_adjbits[128 * Nn];
__device__ float  g_Wh[4 * Nn * 64];
__device__ float  g_Wh2[Nn * 64];
__device__ float4 g_rowdat[4 * Nn];
__device__ float4 g_coldat[4 * Nn];
__device__ float  g_part[32 * Nn * 64];
__device__ float  g_den[32 * Nn];
__device__ float  g_hcat[Nn * 256];
__device__ float  g_xres[Nn * 64];
__device__ float  g_att2[Nn * 64];
__device__ int    g_ctr[2];

__device__ __forceinline__ uint32_t smem_u32(const void* p) {
    uint32_t a;
    asm("{ .reg .u64 t; cvta.to.shared.u64 t, %1; cvt.u32.u64 %0, t; }" : "=r"(a) : "l"(p));
    return a;
}
__device__ __forceinline__ float to_tf32f(float x) {
    uint32_t u; asm("cvt.rna.tf32.f32 %0, %1;" : "=r"(u) : "f"(x));
    return __uint_as_float(u);
}
__device__ __forceinline__ float eluf(float v) { return v > 0.f ? v : expm1f(v); }

#define CP16(d, s) asm volatile("cp.async.ca.shared.global [%0],[%1],16;" :: "r"(d), "l"(s))
#define CP4(d, s)  asm volatile("cp.async.ca.shared.global [%0],[%1],4;"  :: "r"(d), "l"(s))
#define CPCOMMIT() asm volatile("cp.async.commit_group;")
#define CPWAIT1()  asm volatile("cp.async.wait_group 1;" ::: "memory")

__device__ __forceinline__ void mma8(float* c, uint32_t a0, uint32_t a1, uint32_t a2, uint32_t a3,
                                     uint32_t b0, uint32_t b1) {
    asm("mma.sync.aligned.m16n8k8.row.col.f32.tf32.tf32.f32 "
        "{%0,%1,%2,%3},{%4,%5,%6,%7},{%8,%9},{%0,%1,%2,%3};"
        : "+f"(c[0]), "+f"(c[1]), "+f"(c[2]), "+f"(c[3])
        : "r"(a0), "r"(a1), "r"(a2), "r"(a3), "r"(b0), "r"(b1));
}

__global__ void pack_adj(const int* __restrict__ adj) {
    if (blockIdx.x == 0 && threadIdx.x == 0) { g_ctr[0] = 0; g_ctr[1] = 0; }
    int idx = blockIdx.x * 256 + threadIdx.x;
    int i = idx >> 12, j = idx & 4095;
    unsigned w = __ballot_sync(0xFFFFFFFFu, adj[idx] > 0);
    if ((j & 31) == 0) g_adjbits[(j >> 5) * Nn + i] = w;
}

// C = epi((A[+A2]) @ B + bias); tf32out rounds C to tf32 (no bias/elu in that mode)
__global__ __launch_bounds__(256)
void gemm64(const float* __restrict__ A, const float* __restrict__ A2,
            const float* __restrict__ B, const float* __restrict__ bias,
            float* __restrict__ C, int K, int transB, int doElu, int tf32out,
            long Bg, long Cg)
{
    __shared__ __align__(16) float As[16][68];
    __shared__ __align__(16) float Bs[16][68];
    B += (long)blockIdx.y * Bg;  C += (long)blockIdx.y * Cg;
    int tid = threadIdx.x, ibase = blockIdx.x * 64;
    int r0 = (tid >> 4) << 2, c0 = (tid & 15) << 2;
    int ai = tid >> 2, akq = tid & 3;
    float acc[4][4] = {};
    for (int k0 = 0; k0 < K; k0 += 16) {
        __syncthreads();
        float4 v = *(const float4*)&A[(size_t)(ibase + ai) * K + k0 + akq * 4];
        if (A2) { float4 u = *(const float4*)&A2[(size_t)(ibase + ai) * K + k0 + akq * 4];
                  v.x += u.x; v.y += u.y; v.z += u.z; v.w += u.w; }
        As[akq*4+0][ai] = v.x; As[akq*4+1][ai] = v.y; As[akq*4+2][ai] = v.z; As[akq*4+3][ai] = v.w;
        if (!transB) {
            int bk = tid >> 4, bf = (tid & 15) << 2;
            *(float4*)&Bs[bk][bf] = *(const float4*)&B[(size_t)(k0 + bk) * 64 + bf];
        } else {
            int bf = tid >> 2, bkq = tid & 3;
            float4 u = *(const float4*)&B[(size_t)bf * K + k0 + bkq * 4];
            Bs[bkq*4+0][bf] = u.x; Bs[bkq*4+1][bf] = u.y; Bs[bkq*4+2][bf] = u.z; Bs[bkq*4+3][bf] = u.w;
        }
        __syncthreads();
        #pragma unroll
        for (int k = 0; k < 16; ++k) {
            float4 a4 = *(const float4*)&As[k][r0];
            float4 b4 = *(const float4*)&Bs[k][c0];
            acc[0][0]+=a4.x*b4.x; acc[0][1]+=a4.x*b4.y; acc[0][2]+=a4.x*b4.z; acc[0][3]+=a4.x*b4.w;
            acc[1][0]+=a4.y*b4.x; acc[1][1]+=a4.y*b4.y; acc[1][2]+=a4.y*b4.z; acc[1][3]+=a4.y*b4.w;
            acc[2][0]+=a4.z*b4.x; acc[2][1]+=a4.z*b4.y; acc[2][2]+=a4.z*b4.z; acc[2][3]+=a4.z*b4.w;
            acc[3][0]+=a4.w*b4.x; acc[3][1]+=a4.w*b4.y; acc[3][2]+=a4.w*b4.z; acc[3][3]+=a4.w*b4.w;
        }
    }
    float b0 = bias?bias[c0]:0.f, b1 = bias?bias[c0+1]:0.f, b2 = bias?bias[c0+2]:0.f, b3 = bias?bias[c0+3]:0.f;
    #pragma unroll
    for (int r = 0; r < 4; ++r) {
        float4 o = make_float4(acc[r][0]+b0, acc[r][1]+b1, acc[r][2]+b2, acc[r][3]+b3);
        if (tf32out) { o.x=to_tf32f(o.x); o.y=to_tf32f(o.y); o.z=to_tf32f(o.z); o.w=to_tf32f(o.w); }
        if (doElu) { o.x=eluf(o.x); o.y=eluf(o.y); o.z=eluf(o.z); o.w=eluf(o.w); }
        *(float4*)&C[(size_t)(ibase + r0 + r) * 64 + c0] = o;
    }
}

__global__ void rowcol(const float* __restrict__ Wh, const float* __restrict__ a,
                       float4* __restrict__ rowdat, float4* __restrict__ coldat)
{
    __shared__ float as[128];
    int g = blockIdx.y;
    if (threadIdx.x < 128) as[threadIdx.x] = a[g * 128 + threadIdx.x];
    __syncthreads();
    int i = blockIdx.x * 256 + threadIdx.x;
    const float* w = Wh + ((size_t)g * Nn + i) * 64;
    float s1 = 0.f, s2 = 0.f;
    #pragma unroll
    for (int f = 0; f < 64; f += 4) {
        float4 v = *(const float4*)&w[f];
        s1 += v.x*as[f] + v.y*as[f+1] + v.z*as[f+2] + v.w*as[f+3];
        s2 += v.x*as[64+f] + v.y*as[64+f+1] + v.z*as[64+f+2] + v.w*as[64+f+3];
    }
    rowdat[g*Nn+i] = make_float4(s1, expf(s1), expf(LRALPHA*s1), 0.f);
    coldat[g*Nn+i] = make_float4(s2, expf(s2), expf(LRALPHA*s2), 0.f);
}

// masked-softmax aggregation via warp-level tf32 mma.sync, A built in registers
__global__ __launch_bounds__(128)
void gat_attn_mma(const float* __restrict__ Wh, const float4* __restrict__ rowdat,
                  const float4* __restrict__ coldat, float* __restrict__ part,
                  float* __restrict__ den, int G, int ksplit, int layer)
{
    __shared__ __align__(16) float Bsm[2][32 * 72];
    __shared__ unsigned bitsS[2][128];
    __shared__ __align__(16) float4 cdsS[2][32];
    __shared__ int itemS;

    int tid = threadIdx.x, w = tid >> 5, lane = tid & 31;
    int la = lane & 3, lp = lane >> 2;
    uint32_t bsB = smem_u32(&Bsm[0][0]);
    uint32_t btB = smem_u32(&bitsS[0][0]);
    uint32_t cdB = smem_u32(&cdsS[0][0]);

    int jchunk = Nn / ksplit, ntiles = jchunk / 32;
    int nItems = 32 * G * ksplit;

    while (true) {
        if (tid == 0) itemS = atomicAdd(&g_ctr[layer], 1);
        __syncthreads();
        int item = itemS;
        if (item >= nItems) break;
        int ib = item & 31, rest = item >> 5;
        int g = rest % G, ks = rest / G;
        int ibase = ib * 128, jbase0 = ks * jchunk;
        int gN = g * Nn;
        const float* WhG = Wh + (size_t)gN * 64;

        float4 rdv[4];
        #pragma unroll
        for (int h = 0; h < 4; ++h) rdv[h] = rowdat[gN + ibase + w*32 + 8*h + lp];
        float cA[2][8][4];
        #pragma unroll
        for (int m = 0; m < 2; ++m)
            #pragma unroll
            for (int n = 0; n < 8; ++n) { cA[m][n][0]=0.f; cA[m][n][1]=0.f; cA[m][n][2]=0.f; cA[m][n][3]=0.f; }
        float dacc[4] = {0.f, 0.f, 0.f, 0.f};

        auto stage = [&](int jbase, int buf) {
            const float* src = WhG + (size_t)jbase * 64;
            #pragma unroll
            for (int r = 0; r < 4; ++r) {
                int e = tid + 128 * r;
                int j = e >> 4, f = (e & 15) << 2;
                CP16(bsB + (uint32_t)(buf * 2304 + j * 72 + f) * 4, src + j * 64 + f);
            }
            CP4(btB + (uint32_t)(buf * 128 + tid) * 4, &g_adjbits[(jbase >> 5) * Nn + ibase + tid]);
            if (tid < 32) CP16(cdB + (uint32_t)(buf * 32 + tid) * 16, &coldat[gN + jbase + tid]);
            CPCOMMIT();
        };

        stage(jbase0, 0);
        int buf = 0;
        for (int t = 0; t < ntiles; ++t) {
            if (t + 1 < ntiles) stage(jbase0 + (t + 1) * 32, buf ^ 1);
            else CPCOMMIT();
            CPWAIT1();
            __syncthreads();
            unsigned rb[4];
            #pragma unroll
            for (int h = 0; h < 4; ++h) rb[h] = bitsS[buf][w*32 + 8*h + lp];
            const float* bbase = &Bsm[buf][0];
            #pragma unroll
            for (int q = 0; q < 4; ++q) {
                float4 c0 = cdsS[buf][q * 8 + la];
                float4 c1 = cdsS[buf][q * 8 + la + 4];
                uint32_t A0[4], A1[4];
                #pragma unroll
                for (int h = 0; h < 4; ++h) {
                    float w0 = ((rb[h] >> (q*8 + la)) & 1u)
                             ? ((rdv[h].x + c0.x > 0.f) ? rdv[h].y * c0.y : rdv[h].z * c0.z) : 0.f;
                    float w1 = ((rb[h] >> (q*8 + la + 4)) & 1u)
                             ? ((rdv[h].x + c1.x > 0.f) ? rdv[h].y * c1.y : rdv[h].z * c1.z) : 0.f;
                    asm("cvt.rna.tf32.f32 %0, %1;" : "=r"(A0[h]) : "f"(w0));
                    asm("cvt.rna.tf32.f32 %0, %1;" : "=r"(A1[h]) : "f"(w1));
                    dacc[h] += __uint_as_float(A0[h]) + __uint_as_float(A1[h]);
                }
                const float* bp = bbase + (q*8 + la) * 72 + lp;
                #pragma unroll
                for (int n = 0; n < 8; ++n) {
                    uint32_t b0 = __float_as_uint(bp[n * 8]);
                    uint32_t b1 = __float_as_uint(bp[4 * 72 + n * 8]);
                    mma8(cA[0][n], A0[0], A0[1], A1[0], A1[1], b0, b1);
                    mma8(cA[1][n], A0[2], A0[3], A1[2], A1[3], b0, b1);
                }
            }
            __syncthreads();
            buf ^= 1;
        }
        // denominator: reduce over the 4 lanes of each row group
        int p = g * ksplit + ks;
        #pragma unroll
        for (int h = 0; h < 4; ++h) {
            dacc[h] += __shfl_xor_sync(0xFFFFFFFFu, dacc[h], 1);
            dacc[h] += __shfl_xor_sync(0xFFFFFFFFu, dacc[h], 2);
            if (la == 0) den[(size_t)p * Nn + ibase + w*32 + 8*h + lp] = dacc[h];
        }
        // C fragments -> partials
        #pragma unroll
        for (int m = 0; m < 2; ++m) {
            int r0 = ibase + w*32 + 16*m + lp;
            #pragma unroll
            for (int n = 0; n < 8; ++n) {
                float* d0 = &part[((size_t)p * Nn + r0) * 64 + n * 8 + 2 * la];
                *(float2*)d0 = make_float2(cA[m][n][0], cA[m][n][1]);
                *(float2*)(d0 + 8 * 64) = make_float2(cA[m][n][2], cA[m][n][3]);
            }
        }
    }
}

__global__ void combine(const float* __restrict__ part, const float* __restrict__ den,
                        float* __restrict__ dst, int G, int ksplit, int dstStride)
{
    int idx = blockIdx.x * 256 + threadIdx.x;
    int f = idx & 63;
    int g = (idx >> 6) % G;
    int i = idx / (64 * G);
    float s = 0.f, d = 0.f;
    for (int ks = 0; ks < ksplit; ++ks) {
        int p = g * ksplit + ks;
        s += part[((size_t)p * Nn + i) * 64 + f];
        d += den[(size_t)p * Nn + i];
    }
    dst[(size_t)i * dstStride + g * 64 + f] = eluf(s / d);
}

extern "C" void kernel_launch(void* const* d_in, const int* in_sizes, int n_in,
                              void* d_out, int out_size)
{
    const float* x        = (const float*)d_in[0];
    const int*   adj      = (const int*)d_in[1];
    const float* w_heads  = (const float*)d_in[2];
    const float* a_heads  = (const float*)d_in[3];
    const float* w_out    = (const float*)d_in[4];
    const float* a_out    = (const float*)d_in[5];
    const float* lin_w    = (const float*)d_in[6];
    const float* lin_b    = (const float*)d_in[7];
    const float* outlin_w = (const float*)d_in[8];
    const float* outlin_b = (const float*)d_in[9];
    float* out = (float*)d_out;

    float *pWh, *pWh2, *pHcat, *pXres, *pAtt2, *pPart, *pDen;
    float4 *pRow, *pCol;
    cudaGetSymbolAddress((void**)&pWh,   g_Wh);
    cudaGetSymbolAddress((void**)&pWh2,  g_Wh2);
    cudaGetSymbolAddress((void**)&pHcat, g_hcat);
    cudaGetSymbolAddress((void**)&pXres, g_xres);
    cudaGetSymbolAddress((void**)&pAtt2, g_att2);
    cudaGetSymbolAddress((void**)&pPart, g_part);
    cudaGetSymbolAddress((void**)&pDen,  g_den);
    cudaGetSymbolAddress((void**)&pRow,  g_rowdat);
    cudaGetSymbolAddress((void**)&pCol,  g_coldat);

    pack_adj<<<(Nn * Nn) / 256, 256>>>(adj);                       // also resets work counters
    gemm64<<<dim3(Nn/64, 4), 256>>>(x, nullptr, w_heads, nullptr, pWh, 128, 0, 0, 1, 128L*64, (long)Nn*64);
    gemm64<<<dim3(Nn/64, 1), 256>>>(x, nullptr, lin_w, lin_b, pXres, 128, 1, 0, 0, 0, 0);
    rowcol<<<dim3(Nn/256, 4), 256>>>(pWh, a_heads, pRow, pCol);
    gat_attn_mma<<<592, 128>>>(pWh, pRow, pCol, pPart, pDen, 4, 8, 0);
    combine<<<(Nn * 4 * 64) / 256, 256>>>(pPart, pDen, pHcat, 4, 8, 256);
    gemm64<<<dim3(Nn/64, 1), 256>>>(pHcat, nullptr, w_out, nullptr, pWh2, 256, 0, 0, 1, 0, 0);
    rowcol<<<dim3(Nn/256, 1), 256>>>(pWh2, a_out, pRow, pCol);
    gat_attn_mma<<<592, 128>>>(pWh2, pRow, pCol, pPart, pDen, 1, 32, 1);
    combine<<<(Nn * 64) / 256, 256>>>(pPart, pDen, pAtt2, 1, 32, 64);
    gemm64<<<dim3(Nn/64, 1), 256>>>(pXres, pAtt2, outlin_w, outlin_b, out, 64, 1, 1, 0, 0, 0);
}

// round 11
// speedup vs baseline: 3.3255x; 1.3968x over previous
#include <cuda_runtime.h>
#include <cuda_bf16.h>
#include <cstdint>
#include <math.h>

#define Nn 4096
#define LRALPHA 0.2f

__device__ unsigned g_adjbits[128 * Nn];
__device__ float  g_Wh[4 * Nn * 64];
__device__ float  g_Wh2[Nn * 64];
__device__ __nv_bfloat16 g_WhB[4 * 64 * Nn];   // [g][f][node] bf16
__device__ __nv_bfloat16 g_Wh2B[64 * Nn];
__device__ float4 g_rowdat[4 * Nn];
__device__ float4 g_coldat[4 * Nn];
__device__ float  g_part[16 * Nn * 64];
__device__ float  g_den[16 * Nn];
__device__ float  g_hcat[Nn * 256];
__device__ float  g_xres[Nn * 64];
__device__ float  g_att2[Nn * 64];
__device__ int    g_ctr[2];

__device__ __forceinline__ uint32_t smem_u32(const void* p) {
    uint32_t a;
    asm("{ .reg .u64 t; cvta.to.shared.u64 t, %1; cvt.u32.u64 %0, t; }" : "=r"(a) : "l"(p));
    return a;
}
__device__ __forceinline__ float eluf(float v) { return v > 0.f ? v : expm1f(v); }

#define CP16(d, s) asm volatile("cp.async.ca.shared.global [%0],[%1],16;" :: "r"(d), "l"(s))
#define CP4(d, s)  asm volatile("cp.async.ca.shared.global [%0],[%1],4;"  :: "r"(d), "l"(s))
#define CPCOMMIT() asm volatile("cp.async.commit_group;")
#define CPWAIT1()  asm volatile("cp.async.wait_group 1;" ::: "memory")

__device__ __forceinline__ void mma16(float* c, uint32_t a0, uint32_t a1, uint32_t a2, uint32_t a3,
                                      uint32_t b0, uint32_t b1) {
    asm("mma.sync.aligned.m16n8k16.row.col.f32.bf16.bf16.f32 "
        "{%0,%1,%2,%3},{%4,%5,%6,%7},{%8,%9},{%0,%1,%2,%3};"
        : "+f"(c[0]), "+f"(c[1]), "+f"(c[2]), "+f"(c[3])
        : "r"(a0), "r"(a1), "r"(a2), "r"(a3), "r"(b0), "r"(b1));
}
__device__ __forceinline__ uint32_t packbf(float hi, float lo) {
    uint32_t d; asm("cvt.rn.bf16x2.f32 %0, %1, %2;" : "=r"(d) : "f"(hi), "f"(lo));
    return d;
}
__device__ __forceinline__ float bflo(uint32_t v) { return __uint_as_float(v << 16); }
__device__ __forceinline__ float bfhi(uint32_t v) { return __uint_as_float(v & 0xFFFF0000u); }

__global__ void pack_adj(const int* __restrict__ adj) {
    if (blockIdx.x == 0 && threadIdx.x == 0) { g_ctr[0] = 0; g_ctr[1] = 0; }
    int idx = blockIdx.x * 256 + threadIdx.x;
    int i = idx >> 12, j = idx & 4095;
    unsigned w = __ballot_sync(0xFFFFFFFFu, adj[idx] > 0);
    if ((j & 31) == 0) g_adjbits[(j >> 5) * Nn + i] = w;
}

// C = epi((A[+A2]) @ B + bias); if bT: also write C^T as bf16 with leading dim Nn
__global__ __launch_bounds__(256)
void gemm64(const float* __restrict__ A, const float* __restrict__ A2,
            const float* __restrict__ B, const float* __restrict__ bias,
            float* __restrict__ C, int K, int transB, int doElu,
            __nv_bfloat16* __restrict__ bT, long Bg, long Cg, long Tg)
{
    __shared__ __align__(16) float As[16][68];
    __shared__ __align__(16) float Bs[16][68];
    B += (long)blockIdx.y * Bg;  C += (long)blockIdx.y * Cg;
    if (bT) bT += (long)blockIdx.y * Tg;
    int tid = threadIdx.x, ibase = blockIdx.x * 64;
    int r0 = (tid >> 4) << 2, c0 = (tid & 15) << 2;
    int ai = tid >> 2, akq = tid & 3;
    float acc[4][4] = {};
    for (int k0 = 0; k0 < K; k0 += 16) {
        __syncthreads();
        float4 v = *(const float4*)&A[(size_t)(ibase + ai) * K + k0 + akq * 4];
        if (A2) { float4 u = *(const float4*)&A2[(size_t)(ibase + ai) * K + k0 + akq * 4];
                  v.x += u.x; v.y += u.y; v.z += u.z; v.w += u.w; }
        As[akq*4+0][ai] = v.x; As[akq*4+1][ai] = v.y; As[akq*4+2][ai] = v.z; As[akq*4+3][ai] = v.w;
        if (!transB) {
            int bk = tid >> 4, bf = (tid & 15) << 2;
            *(float4*)&Bs[bk][bf] = *(const float4*)&B[(size_t)(k0 + bk) * 64 + bf];
        } else {
            int bf = tid >> 2, bkq = tid & 3;
            float4 u = *(const float4*)&B[(size_t)bf * K + k0 + bkq * 4];
            Bs[bkq*4+0][bf] = u.x; Bs[bkq*4+1][bf] = u.y; Bs[bkq*4+2][bf] = u.z; Bs[bkq*4+3][bf] = u.w;
        }
        __syncthreads();
        #pragma unroll
        for (int k = 0; k < 16; ++k) {
            float4 a4 = *(const float4*)&As[k][r0];
            float4 b4 = *(const float4*)&Bs[k][c0];
            acc[0][0]+=a4.x*b4.x; acc[0][1]+=a4.x*b4.y; acc[0][2]+=a4.x*b4.z; acc[0][3]+=a4.x*b4.w;
            acc[1][0]+=a4.y*b4.x; acc[1][1]+=a4.y*b4.y; acc[1][2]+=a4.y*b4.z; acc[1][3]+=a4.y*b4.w;
            acc[2][0]+=a4.z*b4.x; acc[2][1]+=a4.z*b4.y; acc[2][2]+=a4.z*b4.z; acc[2][3]+=a4.z*b4.w;
            acc[3][0]+=a4.w*b4.x; acc[3][1]+=a4.w*b4.y; acc[3][2]+=a4.w*b4.z; acc[3][3]+=a4.w*b4.w;
        }
    }
    float b0 = bias?bias[c0]:0.f, b1 = bias?bias[c0+1]:0.f, b2 = bias?bias[c0+2]:0.f, b3 = bias?bias[c0+3]:0.f;
    #pragma unroll
    for (int r = 0; r < 4; ++r) {
        float4 o = make_float4(acc[r][0]+b0, acc[r][1]+b1, acc[r][2]+b2, acc[r][3]+b3);
        if (doElu) { o.x=eluf(o.x); o.y=eluf(o.y); o.z=eluf(o.z); o.w=eluf(o.w); }
        *(float4*)&C[(size_t)(ibase + r0 + r) * 64 + c0] = o;
    }
    if (bT) {
        #pragma unroll
        for (int c = 0; c < 4; ++c) {
            ushort4 h;
            h.x = __bfloat16_as_ushort(__float2bfloat16_rn(acc[0][c]));
            h.y = __bfloat16_as_ushort(__float2bfloat16_rn(acc[1][c]));
            h.z = __bfloat16_as_ushort(__float2bfloat16_rn(acc[2][c]));
            h.w = __bfloat16_as_ushort(__float2bfloat16_rn(acc[3][c]));
            *(ushort4*)&bT[(size_t)(c0 + c) * Nn + ibase + r0] = h;
        }
    }
}

__global__ void rowcol(const float* __restrict__ Wh, const float* __restrict__ a,
                       float4* __restrict__ rowdat, float4* __restrict__ coldat)
{
    __shared__ float as[128];
    int g = blockIdx.y;
    if (threadIdx.x < 128) as[threadIdx.x] = a[g * 128 + threadIdx.x];
    __syncthreads();
    int i = blockIdx.x * 256 + threadIdx.x;
    const float* w = Wh + ((size_t)g * Nn + i) * 64;
    float s1 = 0.f, s2 = 0.f;
    #pragma unroll
    for (int f = 0; f < 64; f += 4) {
        float4 v = *(const float4*)&w[f];
        s1 += v.x*as[f] + v.y*as[f+1] + v.z*as[f+2] + v.w*as[f+3];
        s2 += v.x*as[64+f] + v.y*as[64+f+1] + v.z*as[64+f+2] + v.w*as[64+f+3];
    }
    rowdat[g*Nn+i] = make_float4(s1, expf(s1), expf(LRALPHA*s1), 0.f);
    coldat[g*Nn+i] = make_float4(s2, expf(s2), expf(LRALPHA*s2), 0.f);
}

// masked-softmax aggregation: bf16 m16n8k16 mma.sync, A built in registers
// B SMEM: [f][j] bf16, row stride 40 bf16 (80B) -> conflict-free (20*lp+la) banks
__global__ __launch_bounds__(128)
void gat_attn_mma(const __nv_bfloat16* __restrict__ WhB, const float4* __restrict__ rowdat,
                  const float4* __restrict__ coldat, float* __restrict__ part,
                  float* __restrict__ den, int G, int ksplit, int layer)
{
    __shared__ __align__(16) __nv_bfloat16 Bsm[2][64 * 40];
    __shared__ unsigned bitsS[2][128];
    __shared__ __align__(16) float4 cdsS[2][32];
    __shared__ int itemS;

    int tid = threadIdx.x, w = tid >> 5, lane = tid & 31;
    int la = lane & 3, lp = lane >> 2;
    uint32_t bsB = smem_u32(&Bsm[0][0]);
    uint32_t btB = smem_u32(&bitsS[0][0]);
    uint32_t cdB = smem_u32(&cdsS[0][0]);

    int jchunk = Nn / ksplit, ntiles = jchunk / 32;
    int nItems = 32 * G * ksplit;

    while (true) {
        if (tid == 0) itemS = atomicAdd(&g_ctr[layer], 1);
        __syncthreads();
        int item = itemS;
        if (item >= nItems) break;
        int ib = item & 31, rest = item >> 5;
        int g = rest % G, ks = rest / G;
        int ibase = ib * 128, jbase0 = ks * jchunk;
        int gN = g * Nn;
        const __nv_bfloat16* WhBg = WhB + (size_t)g * 64 * Nn;

        float4 rdv[4];
        #pragma unroll
        for (int h = 0; h < 4; ++h) rdv[h] = rowdat[gN + ibase + w*32 + 8*h + lp];
        float cA[2][8][4];
        #pragma unroll
        for (int m = 0; m < 2; ++m)
            #pragma unroll
            for (int n = 0; n < 8; ++n) { cA[m][n][0]=0.f; cA[m][n][1]=0.f; cA[m][n][2]=0.f; cA[m][n][3]=0.f; }
        float dacc[4] = {0.f, 0.f, 0.f, 0.f};

        auto stage = [&](int jbase, int buf) {
            #pragma unroll
            for (int r = 0; r < 2; ++r) {
                int e = tid + 128 * r;
                int f = e >> 2, ch = e & 3;
                CP16(bsB + (uint32_t)(buf * 5120 + f * 80 + ch * 16),
                     WhBg + (size_t)f * Nn + jbase + ch * 8);
            }
            CP4(btB + (uint32_t)(buf * 128 + tid) * 4, &g_adjbits[(jbase >> 5) * Nn + ibase + tid]);
            if (tid < 32) CP16(cdB + (uint32_t)(buf * 32 + tid) * 16, &coldat[gN + jbase + tid]);
            CPCOMMIT();
        };

        stage(jbase0, 0);
        int buf = 0;
        for (int t = 0; t < ntiles; ++t) {
            if (t + 1 < ntiles) stage(jbase0 + (t + 1) * 32, buf ^ 1);
            else CPCOMMIT();
            CPWAIT1();
            __syncthreads();
            unsigned rb[4];
            #pragma unroll
            for (int h = 0; h < 4; ++h) rb[h] = bitsS[buf][w*32 + 8*h + lp];
            const __nv_bfloat16* bbase = &Bsm[buf][0];
            #pragma unroll
            for (int ks2 = 0; ks2 < 2; ++ks2) {
                int jk = ks2 * 16;
                float4 c0 = cdsS[buf][jk + 2*la];
                float4 c1 = cdsS[buf][jk + 2*la + 1];
                float4 c2 = cdsS[buf][jk + 2*la + 8];
                float4 c3 = cdsS[buf][jk + 2*la + 9];
                uint32_t Alo[4], Ahi[4];
                #pragma unroll
                for (int h = 0; h < 4; ++h) {
                    int jb = jk + 2*la;
                    float rx = rdv[h].x, ry = rdv[h].y, rz = rdv[h].z;
                    float w0 = ((rb[h] >> jb) & 1u)       ? ((rx + c0.x > 0.f) ? ry*c0.y : rz*c0.z) : 0.f;
                    float w1 = ((rb[h] >> (jb+1)) & 1u)   ? ((rx + c1.x > 0.f) ? ry*c1.y : rz*c1.z) : 0.f;
                    float w2 = ((rb[h] >> (jb+8)) & 1u)   ? ((rx + c2.x > 0.f) ? ry*c2.y : rz*c2.z) : 0.f;
                    float w3 = ((rb[h] >> (jb+9)) & 1u)   ? ((rx + c3.x > 0.f) ? ry*c3.y : rz*c3.z) : 0.f;
                    Alo[h] = packbf(w1, w0);
                    Ahi[h] = packbf(w3, w2);
                    dacc[h] += bflo(Alo[h]) + bfhi(Alo[h]) + bflo(Ahi[h]) + bfhi(Ahi[h]);
                }
                #pragma unroll
                for (int n = 0; n < 8; ++n) {
                    const __nv_bfloat16* bp = bbase + (n*8 + lp) * 40 + jk + 2*la;
                    uint32_t b0 = *(const uint32_t*)bp;
                    uint32_t b1 = *(const uint32_t*)(bp + 8);
                    mma16(cA[0][n], Alo[0], Alo[1], Ahi[0], Ahi[1], b0, b1);
                    mma16(cA[1][n], Alo[2], Alo[3], Ahi[2], Ahi[3], b0, b1);
                }
            }
            __syncthreads();
            buf ^= 1;
        }
        int p = g * ksplit + ks;
        #pragma unroll
        for (int h = 0; h < 4; ++h) {
            dacc[h] += __shfl_xor_sync(0xFFFFFFFFu, dacc[h], 1);
            dacc[h] += __shfl_xor_sync(0xFFFFFFFFu, dacc[h], 2);
            if (la == 0) den[(size_t)p * Nn + ibase + w*32 + 8*h + lp] = dacc[h];
        }
        #pragma unroll
        for (int m = 0; m < 2; ++m) {
            int r0 = ibase + w*32 + 16*m + lp;
            #pragma unroll
            for (int n = 0; n < 8; ++n) {
                float* d0 = &part[((size_t)p * Nn + r0) * 64 + n*8 + 2*la];
                *(float2*)d0 = make_float2(cA[m][n][0], cA[m][n][1]);
                *(float2*)(d0 + 8 * 64) = make_float2(cA[m][n][2], cA[m][n][3]);
            }
        }
    }
}

__global__ void combine(const float* __restrict__ part, const float* __restrict__ den,
                        float* __restrict__ dst, int G, int ksplit, int dstStride)
{
    int idx = blockIdx.x * 256 + threadIdx.x;
    int f = idx & 63;
    int g = (idx >> 6) % G;
    int i = idx / (64 * G);
    float s = 0.f, d = 0.f;
    for (int ks = 0; ks < ksplit; ++ks) {
        int p = g * ksplit + ks;
        s += part[((size_t)p * Nn + i) * 64 + f];
        d += den[(size_t)p * Nn + i];
    }
    dst[(size_t)i * dstStride + g * 64 + f] = eluf(s / d);
}

extern "C" void kernel_launch(void* const* d_in, const int* in_sizes, int n_in,
                              void* d_out, int out_size)
{
    const float* x        = (const float*)d_in[0];
    const int*   adj      = (const int*)d_in[1];
    const float* w_heads  = (const float*)d_in[2];
    const float* a_heads  = (const float*)d_in[3];
    const float* w_out    = (const float*)d_in[4];
    const float* a_out    = (const float*)d_in[5];
    const float* lin_w    = (const float*)d_in[6];
    const float* lin_b    = (const float*)d_in[7];
    const float* outlin_w = (const float*)d_in[8];
    const float* outlin_b = (const float*)d_in[9];
    float* out = (float*)d_out;

    float *pWh, *pWh2, *pHcat, *pXres, *pAtt2, *pPart, *pDen;
    __nv_bfloat16 *pWhB, *pWh2B;
    float4 *pRow, *pCol;
    cudaGetSymbolAddress((void**)&pWh,   g_Wh);
    cudaGetSymbolAddress((void**)&pWh2,  g_Wh2);
    cudaGetSymbolAddress((void**)&pWhB,  g_WhB);
    cudaGetSymbolAddress((void**)&pWh2B, g_Wh2B);
    cudaGetSymbolAddress((void**)&pHcat, g_hcat);
    cudaGetSymbolAddress((void**)&pXres, g_xres);
    cudaGetSymbolAddress((void**)&pAtt2, g_att2);
    cudaGetSymbolAddress((void**)&pPart, g_part);
    cudaGetSymbolAddress((void**)&pDen,  g_den);
    cudaGetSymbolAddress((void**)&pRow,  g_rowdat);
    cudaGetSymbolAddress((void**)&pCol,  g_coldat);

    pack_adj<<<(Nn * Nn) / 256, 256>>>(adj);
    gemm64<<<dim3(Nn/64, 4), 256>>>(x, nullptr, w_heads, nullptr, pWh, 128, 0, 0,
                                    pWhB, 128L*64, (long)Nn*64, 64L*Nn);
    gemm64<<<dim3(Nn/64, 1), 256>>>(x, nullptr, lin_w, lin_b, pXres, 128, 1, 0,
                                    nullptr, 0, 0, 0);
    rowcol<<<dim3(Nn/256, 4), 256>>>(pWh, a_heads, pRow, pCol);
    gat_attn_mma<<<592, 128>>>(pWhB, pRow, pCol, pPart, pDen, 4, 4, 0);
    combine<<<(Nn * 4 * 64) / 256, 256>>>(pPart, pDen, pHcat, 4, 4, 256);
    gemm64<<<dim3(Nn/64, 1), 256>>>(pHcat, nullptr, w_out, nullptr, pWh2, 256, 0, 0,
                                    pWh2B, 0, 0, 0);
    rowcol<<<dim3(Nn/256, 1), 256>>>(pWh2, a_out, pRow, pCol);
    gat_attn_mma<<<592, 128>>>(pWh2B, pRow, pCol, pPart, pDen, 1, 16, 1);
    combine<<<(Nn * 64) / 256, 256>>>(pPart, pDen, pAtt2, 1, 16, 64);
    gemm64<<<dim3(Nn/64, 1), 256>>>(pXres, pAtt2, outlin_w, outlin_b, out, 64, 1, 1,
                                    nullptr, 0, 0, 0);
}

// round 12
// speedup vs baseline: 3.6656x; 1.1023x over previous
#include <cuda_runtime.h>
#include <cuda_bf16.h>
#include <cstdint>
#include <math.h>

#define Nn 4096
#define LRALPHA 0.2f
#define ONES2 0x3F803F80u

__device__ unsigned g_adjbits[128 * Nn];
__device__ __nv_bfloat16 g_WhB[4 * 64 * Nn];   // [g][f][node]
__device__ __nv_bfloat16 g_Wh2B[64 * Nn];
__device__ float4 g_rowdat[4 * Nn];            // (s1, e^s1, e^{.2 s1}, _)
__device__ float4 g_coldat[4 * Nn];
__device__ float  g_part[16 * Nn * 64];
__device__ float  g_den[16 * Nn];
__device__ float  g_hcat[Nn * 256];
__device__ float  g_xres[Nn * 64];
__device__ float  g_att2[Nn * 64];
__device__ int    g_ctr[2];

__device__ __forceinline__ uint32_t smem_u32(const void* p) {
    uint32_t a;
    asm("{ .reg .u64 t; cvta.to.shared.u64 t, %1; cvt.u32.u64 %0, t; }" : "=r"(a) : "l"(p));
    return a;
}
__device__ __forceinline__ float eluf(float v) { return v > 0.f ? v : expm1f(v); }
__device__ __forceinline__ float slctf(float a, float b, float c) {
    float d; asm("slct.f32.f32 %0,%1,%2,%3;" : "=f"(d) : "f"(a), "f"(b), "f"(c)); return d;
}
__device__ __forceinline__ float slcti(float a, float b, int c) {
    float d; asm("slct.f32.s32 %0,%1,%2,%3;" : "=f"(d) : "f"(a), "f"(b), "r"(c)); return d;
}

#define CP16(d, s) asm volatile("cp.async.ca.shared.global [%0],[%1],16;" :: "r"(d), "l"(s))
#define CP4(d, s)  asm volatile("cp.async.ca.shared.global [%0],[%1],4;"  :: "r"(d), "l"(s))
#define CPCOMMIT() asm volatile("cp.async.commit_group;")
#define CPWAIT1()  asm volatile("cp.async.wait_group 1;" ::: "memory")

__device__ __forceinline__ void mma16(float* c, uint32_t a0, uint32_t a1, uint32_t a2, uint32_t a3,
                                      uint32_t b0, uint32_t b1) {
    asm("mma.sync.aligned.m16n8k16.row.col.f32.bf16.bf16.f32 "
        "{%0,%1,%2,%3},{%4,%5,%6,%7},{%8,%9},{%0,%1,%2,%3};"
        : "+f"(c[0]), "+f"(c[1]), "+f"(c[2]), "+f"(c[3])
        : "r"(a0), "r"(a1), "r"(a2), "r"(a3), "r"(b0), "r"(b1));
}
__device__ __forceinline__ uint32_t packbf(float hi, float lo) {
    uint32_t d; asm("cvt.rn.bf16x2.f32 %0, %1, %2;" : "=r"(d) : "f"(hi), "f"(lo));
    return d;
}

__global__ void pack_adj(const int* __restrict__ adj) {
    if (blockIdx.x == 0 && threadIdx.x == 0) { g_ctr[0] = 0; g_ctr[1] = 0; }
    int idx = blockIdx.x * 256 + threadIdx.x;
    int i = idx >> 12, j = idx & 4095;
    unsigned w = __ballot_sync(0xFFFFFFFFu, adj[idx] > 0);
    if ((j & 31) == 0) g_adjbits[(j >> 5) * Nn + i] = w;
}

// C = epi((A[+A2]) @ B + bias)  [C may be null]
// bT  != null: also write C^T as bf16, leading dim Nn
// aV  != null: fused attention-score epilogue -> rowdat/coldat (aV stride Ag per blockIdx.y)
__global__ __launch_bounds__(256)
void gemm64(const float* __restrict__ A, const float* __restrict__ A2,
            const float* __restrict__ B, const float* __restrict__ bias,
            float* __restrict__ C, int K, int transB, int doElu,
            __nv_bfloat16* __restrict__ bT,
            const float* __restrict__ aV, float4* __restrict__ rowdat, float4* __restrict__ coldat,
            long Bg, long Cg, long Tg, long Ag)
{
    __shared__ __align__(16) float As[16][68];
    __shared__ __align__(16) float Bs[16][68];
    int gy = blockIdx.y;
    B += (long)gy * Bg;
    if (C)  C  += (long)gy * Cg;
    if (bT) bT += (long)gy * Tg;
    if (aV) { aV += (long)gy * Ag; rowdat += (long)gy * Nn; coldat += (long)gy * Nn; }
    int tid = threadIdx.x, ibase = blockIdx.x * 64;
    int r0 = (tid >> 4) << 2, c0 = (tid & 15) << 2;
    int ai = tid >> 2, akq = tid & 3;
    float acc[4][4] = {};
    for (int k0 = 0; k0 < K; k0 += 16) {
        __syncthreads();
        float4 v = *(const float4*)&A[(size_t)(ibase + ai) * K + k0 + akq * 4];
        if (A2) { float4 u = *(const float4*)&A2[(size_t)(ibase + ai) * K + k0 + akq * 4];
                  v.x += u.x; v.y += u.y; v.z += u.z; v.w += u.w; }
        As[akq*4+0][ai] = v.x; As[akq*4+1][ai] = v.y; As[akq*4+2][ai] = v.z; As[akq*4+3][ai] = v.w;
        if (!transB) {
            int bk = tid >> 4, bf = (tid & 15) << 2;
            *(float4*)&Bs[bk][bf] = *(const float4*)&B[(size_t)(k0 + bk) * 64 + bf];
        } else {
            int bf = tid >> 2, bkq = tid & 3;
            float4 u = *(const float4*)&B[(size_t)bf * K + k0 + bkq * 4];
            Bs[bkq*4+0][bf] = u.x; Bs[bkq*4+1][bf] = u.y; Bs[bkq*4+2][bf] = u.z; Bs[bkq*4+3][bf] = u.w;
        }
        __syncthreads();
        #pragma unroll
        for (int k = 0; k < 16; ++k) {
            float4 a4 = *(const float4*)&As[k][r0];
            float4 b4 = *(const float4*)&Bs[k][c0];
            acc[0][0]+=a4.x*b4.x; acc[0][1]+=a4.x*b4.y; acc[0][2]+=a4.x*b4.z; acc[0][3]+=a4.x*b4.w;
            acc[1][0]+=a4.y*b4.x; acc[1][1]+=a4.y*b4.y; acc[1][2]+=a4.y*b4.z; acc[1][3]+=a4.y*b4.w;
            acc[2][0]+=a4.z*b4.x; acc[2][1]+=a4.z*b4.y; acc[2][2]+=a4.z*b4.z; acc[2][3]+=a4.z*b4.w;
            acc[3][0]+=a4.w*b4.x; acc[3][1]+=a4.w*b4.y; acc[3][2]+=a4.w*b4.z; acc[3][3]+=a4.w*b4.w;
        }
    }
    if (C) {
        float b0 = bias?bias[c0]:0.f, b1 = bias?bias[c0+1]:0.f, b2 = bias?bias[c0+2]:0.f, b3 = bias?bias[c0+3]:0.f;
        #pragma unroll
        for (int r = 0; r < 4; ++r) {
            float4 o = make_float4(acc[r][0]+b0, acc[r][1]+b1, acc[r][2]+b2, acc[r][3]+b3);
            if (doElu) { o.x=eluf(o.x); o.y=eluf(o.y); o.z=eluf(o.z); o.w=eluf(o.w); }
            *(float4*)&C[(size_t)(ibase + r0 + r) * 64 + c0] = o;
        }
    }
    if (bT) {
        #pragma unroll
        for (int c = 0; c < 4; ++c) {
            ushort4 h;
            h.x = __bfloat16_as_ushort(__float2bfloat16_rn(acc[0][c]));
            h.y = __bfloat16_as_ushort(__float2bfloat16_rn(acc[1][c]));
            h.z = __bfloat16_as_ushort(__float2bfloat16_rn(acc[2][c]));
            h.w = __bfloat16_as_ushort(__float2bfloat16_rn(acc[3][c]));
            *(ushort4*)&bT[(size_t)(c0 + c) * Nn + ibase + r0] = h;
        }
    }
    if (aV) {
        float s1[4], s2[4];
        #pragma unroll
        for (int r = 0; r < 4; ++r) {
            s1[r] = acc[r][0]*aV[c0] + acc[r][1]*aV[c0+1] + acc[r][2]*aV[c0+2] + acc[r][3]*aV[c0+3];
            s2[r] = acc[r][0]*aV[64+c0] + acc[r][1]*aV[64+c0+1] + acc[r][2]*aV[64+c0+2] + acc[r][3]*aV[64+c0+3];
            #pragma unroll
            for (int off = 1; off < 16; off <<= 1) {
                s1[r] += __shfl_xor_sync(0xFFFFFFFFu, s1[r], off, 16);
                s2[r] += __shfl_xor_sync(0xFFFFFFFFu, s2[r], off, 16);
            }
        }
        if ((tid & 15) == 0) {
            #pragma unroll
            for (int r = 0; r < 4; ++r) {
                int row = ibase + r0 + r;
                rowdat[row] = make_float4(s1[r], expf(s1[r]), expf(LRALPHA*s1[r]), 0.f);
                coldat[row] = make_float4(s2[r], expf(s2[r]), expf(LRALPHA*s2[r]), 0.f);
            }
        }
    }
}

// masked-softmax aggregation: bf16 m16n8k16 mma.sync, A built in registers,
// denominator via all-ones B fragment MMA. TJ=64 per stage.
__global__ __launch_bounds__(128)
void gat_attn_mma(const __nv_bfloat16* __restrict__ WhB, const float4* __restrict__ rowdat,
                  const float4* __restrict__ coldat, float* __restrict__ part,
                  float* __restrict__ den, int G, int ksplit, int layer)
{
    __shared__ __align__(16) __nv_bfloat16 Bsm[2][64 * 72];
    __shared__ unsigned bitsS[2][2][128];
    __shared__ __align__(16) float4 cdsS[2][64];
    __shared__ int itemS;

    int tid = threadIdx.x, w = tid >> 5, lane = tid & 31;
    int la = lane & 3, lp = lane >> 2;
    uint32_t bsB = smem_u32(&Bsm[0][0]);
    uint32_t btB = smem_u32(&bitsS[0][0][0]);
    uint32_t cdB = smem_u32(&cdsS[0][0]);

    int jchunk = Nn / ksplit, ntiles = jchunk / 64;
    int nItems = 32 * G * ksplit;

    while (true) {
        if (tid == 0) itemS = atomicAdd(&g_ctr[layer], 1);
        __syncthreads();
        int item = itemS;
        if (item >= nItems) break;
        int ib = item & 31, rest = item >> 5;
        int g = rest % G, ks = rest / G;
        int ibase = ib * 128, jbase0 = ks * jchunk;
        int gN = g * Nn;
        const __nv_bfloat16* WhBg = WhB + (size_t)g * 64 * Nn;

        float4 rdv[4];
        #pragma unroll
        for (int h = 0; h < 4; ++h) rdv[h] = rowdat[gN + ibase + w*32 + 8*h + lp];
        float cA[2][8][4];
        float cD[2][4];
        #pragma unroll
        for (int m = 0; m < 2; ++m) {
            #pragma unroll
            for (int n = 0; n < 8; ++n) { cA[m][n][0]=0.f; cA[m][n][1]=0.f; cA[m][n][2]=0.f; cA[m][n][3]=0.f; }
            cD[m][0]=0.f; cD[m][1]=0.f; cD[m][2]=0.f; cD[m][3]=0.f;
        }

        auto stage = [&](int jbase, int buf) {
            #pragma unroll
            for (int r = 0; r < 4; ++r) {
                int e = tid + 128 * r;
                int f = e >> 3, ch = e & 7;
                CP16(bsB + (uint32_t)(buf * 9216 + f * 144 + ch * 16),
                     WhBg + (size_t)f * Nn + jbase + ch * 8);
            }
            CP4(btB + (uint32_t)((buf*2+0)*512 + tid*4), &g_adjbits[((jbase>>5)+0)*Nn + ibase + tid]);
            CP4(btB + (uint32_t)((buf*2+1)*512 + tid*4), &g_adjbits[((jbase>>5)+1)*Nn + ibase + tid]);
            if (tid < 64) CP16(cdB + (uint32_t)(buf*64 + tid)*16, &coldat[gN + jbase + tid]);
            CPCOMMIT();
        };

        stage(jbase0, 0);
        int buf = 0;
        for (int t = 0; t < ntiles; ++t) {
            if (t + 1 < ntiles) stage(jbase0 + (t + 1) * 64, buf ^ 1);
            else CPCOMMIT();
            CPWAIT1();
            __syncthreads();
            unsigned rbw[2][4];
            #pragma unroll
            for (int h = 0; h < 4; ++h) {
                rbw[0][h] = bitsS[buf][0][w*32 + 8*h + lp];
                rbw[1][h] = bitsS[buf][1][w*32 + 8*h + lp];
            }
            const __nv_bfloat16* bbase = &Bsm[buf][0];
            #pragma unroll
            for (int ks2 = 0; ks2 < 4; ++ks2) {
                int jk = ks2 * 16;
                int jl = (jk & 31) + 2*la;
                int wsel = ks2 >> 1;
                float4 c0 = cdsS[buf][jk + 2*la];
                float4 c1 = cdsS[buf][jk + 2*la + 1];
                float4 c2 = cdsS[buf][jk + 2*la + 8];
                float4 c3 = cdsS[buf][jk + 2*la + 9];
                uint32_t Alo[4], Ahi[4];
                #pragma unroll
                for (int h = 0; h < 4; ++h) {
                    unsigned rb = rbw[wsel][h];
                    float rx = rdv[h].x, ry = rdv[h].y, rz = rdv[h].z;
                    float p0 = slctf(ry*c0.y, rz*c0.z, rx + c0.x);
                    float p1 = slctf(ry*c1.y, rz*c1.z, rx + c1.x);
                    float p2 = slctf(ry*c2.y, rz*c2.z, rx + c2.x);
                    float p3 = slctf(ry*c3.y, rz*c3.z, rx + c3.x);
                    float w0 = slcti(0.f, p0, (int)(rb << (31 - jl)));
                    float w1 = slcti(0.f, p1, (int)(rb << (30 - jl)));
                    float w2 = slcti(0.f, p2, (int)(rb << (23 - jl)));
                    float w3 = slcti(0.f, p3, (int)(rb << (22 - jl)));
                    Alo[h] = packbf(w1, w0);
                    Ahi[h] = packbf(w3, w2);
                }
                #pragma unroll
                for (int n = 0; n < 8; ++n) {
                    const __nv_bfloat16* bp = bbase + (n*8 + lp) * 72 + jk + 2*la;
                    uint32_t b0 = *(const uint32_t*)bp;
                    uint32_t b1 = *(const uint32_t*)(bp + 8);
                    mma16(cA[0][n], Alo[0], Alo[1], Ahi[0], Ahi[1], b0, b1);
                    mma16(cA[1][n], Alo[2], Alo[3], Ahi[2], Ahi[3], b0, b1);
                }
                mma16(cD[0], Alo[0], Alo[1], Ahi[0], Ahi[1], ONES2, ONES2);
                mma16(cD[1], Alo[2], Alo[3], Ahi[2], Ahi[3], ONES2, ONES2);
            }
            __syncthreads();
            buf ^= 1;
        }
        int p = g * ksplit + ks;
        if (la == 0) {
            int r = ibase + w*32 + lp;
            den[(size_t)p * Nn + r]      = cD[0][0];
            den[(size_t)p * Nn + r + 8]  = cD[0][2];
            den[(size_t)p * Nn + r + 16] = cD[1][0];
            den[(size_t)p * Nn + r + 24] = cD[1][2];
        }
        #pragma unroll
        for (int m = 0; m < 2; ++m) {
            int r0 = ibase + w*32 + 16*m + lp;
            #pragma unroll
            for (int n = 0; n < 8; ++n) {
                float* d0 = &part[((size_t)p * Nn + r0) * 64 + n*8 + 2*la];
                *(float2*)d0 = make_float2(cA[m][n][0], cA[m][n][1]);
                *(float2*)(d0 + 8 * 64) = make_float2(cA[m][n][2], cA[m][n][3]);
            }
        }
    }
}

__global__ void combine(const float* __restrict__ part, const float* __restrict__ den,
                        float* __restrict__ dst, int G, int ksplit, int dstStride)
{
    int idx = blockIdx.x * 256 + threadIdx.x;
    int f = idx & 63;
    int g = (idx >> 6) % G;
    int i = idx / (64 * G);
    float s = 0.f, d = 0.f;
    for (int ks = 0; ks < ksplit; ++ks) {
        int p = g * ksplit + ks;
        s += part[((size_t)p * Nn + i) * 64 + f];
        d += den[(size_t)p * Nn + i];
    }
    dst[(size_t)i * dstStride + g * 64 + f] = eluf(s / d);
}

extern "C" void kernel_launch(void* const* d_in, const int* in_sizes, int n_in,
                              void* d_out, int out_size)
{
    const float* x        = (const float*)d_in[0];
    const int*   adj      = (const int*)d_in[1];
    const float* w_heads  = (const float*)d_in[2];
    const float* a_heads  = (const float*)d_in[3];
    const float* w_out    = (const float*)d_in[4];
    const float* a_out    = (const float*)d_in[5];
    const float* lin_w    = (const float*)d_in[6];
    const float* lin_b    = (const float*)d_in[7];
    const float* outlin_w = (const float*)d_in[8];
    const float* outlin_b = (const float*)d_in[9];
    float* out = (float*)d_out;

    float *pHcat, *pXres, *pAtt2, *pPart, *pDen;
    __nv_bfloat16 *pWhB, *pWh2B;
    float4 *pRow, *pCol;
    cudaGetSymbolAddress((void**)&pWhB,  g_WhB);
    cudaGetSymbolAddress((void**)&pWh2B, g_Wh2B);
    cudaGetSymbolAddress((void**)&pHcat, g_hcat);
    cudaGetSymbolAddress((void**)&pXres, g_xres);
    cudaGetSymbolAddress((void**)&pAtt2, g_att2);
    cudaGetSymbolAddress((void**)&pPart, g_part);
    cudaGetSymbolAddress((void**)&pDen,  g_den);
    cudaGetSymbolAddress((void**)&pRow,  g_rowdat);
    cudaGetSymbolAddress((void**)&pCol,  g_coldat);

    pack_adj<<<(Nn * Nn) / 256, 256>>>(adj);
    // layer-1: Wh per head -> bf16 transposed + fused scores (no fp32 Wh)
    gemm64<<<dim3(Nn/64, 4), 256>>>(x, nullptr, w_heads, nullptr, nullptr, 128, 0, 0,
                                    pWhB, a_heads, pRow, pCol,
                                    128L*64, 0, 64L*Nn, 128);
    gemm64<<<dim3(Nn/64, 1), 256>>>(x, nullptr, lin_w, lin_b, pXres, 128, 1, 0,
                                    nullptr, nullptr, nullptr, nullptr, 0, 0, 0, 0);
    gat_attn_mma<<<592, 128>>>(pWhB, pRow, pCol, pPart, pDen, 4, 4, 0);
    combine<<<(Nn * 4 * 64) / 256, 256>>>(pPart, pDen, pHcat, 4, 4, 256);
    // layer-2: Wh2 -> bf16 transposed + fused scores
    gemm64<<<dim3(Nn/64, 1), 256>>>(pHcat, nullptr, w_out, nullptr, nullptr, 256, 0, 0,
                                    pWh2B, a_out, pRow, pCol, 0, 0, 0, 0);
    gat_attn_mma<<<592, 128>>>(pWh2B, pRow, pCol, pPart, pDen, 1, 16, 1);
    combine<<<(Nn * 64) / 256, 256>>>(pPart, pDen, pAtt2, 1, 16, 64);
    gemm64<<<dim3(Nn/64, 1), 256>>>(pXres, pAtt2, outlin_w, outlin_b, out, 64, 1, 1,
                                    nullptr, nullptr, nullptr, nullptr, 0, 0, 0, 0);
}

// round 13
// speedup vs baseline: 3.7611x; 1.0260x over previous
#include <cuda_runtime.h>
#include <cuda_bf16.h>
#include <cstdint>
#include <math.h>

#define Nn 4096
#define LRALPHA 0.2f
#define ONES2 0x3F803F80u

__device__ unsigned g_adjbits[128 * Nn];
__device__ __nv_bfloat16 g_WhB[4 * 64 * Nn];   // [g][f][node]
__device__ __nv_bfloat16 g_Wh2B[64 * Nn];
__device__ float4 g_rowdat[4 * Nn];            // (s1, e^s1, e^{.2 s1}, _)
__device__ float4 g_coldat[4 * Nn];
__device__ float  g_part[16 * Nn * 64];
__device__ float  g_den[16 * Nn];
__device__ float  g_hcat[Nn * 256];
__device__ float  g_xres[Nn * 64];
__device__ float  g_att2[Nn * 64];
__device__ int    g_ctr[2];

__device__ __forceinline__ uint32_t smem_u32(const void* p) {
    uint32_t a;
    asm("{ .reg .u64 t; cvta.to.shared.u64 t, %1; cvt.u32.u64 %0, t; }" : "=r"(a) : "l"(p));
    return a;
}
__device__ __forceinline__ float eluf(float v) { return v > 0.f ? v : expm1f(v); }
__device__ __forceinline__ float slctf(float a, float b, float c) {
    float d; asm("slct.f32.f32 %0,%1,%2,%3;" : "=f"(d) : "f"(a), "f"(b), "f"(c)); return d;
}
__device__ __forceinline__ float slcti(float a, float b, int c) {
    float d; asm("slct.f32.s32 %0,%1,%2,%3;" : "=f"(d) : "f"(a), "f"(b), "r"(c)); return d;
}

#define CP16(d, s) asm volatile("cp.async.ca.shared.global [%0],[%1],16;" :: "r"(d), "l"(s))
#define CP4(d, s)  asm volatile("cp.async.ca.shared.global [%0],[%1],4;"  :: "r"(d), "l"(s))
#define CPCOMMIT() asm volatile("cp.async.commit_group;")
#define CPWAIT1()  asm volatile("cp.async.wait_group 1;" ::: "memory")

__device__ __forceinline__ void mma16(float* c, uint32_t a0, uint32_t a1, uint32_t a2, uint32_t a3,
                                      uint32_t b0, uint32_t b1) {
    asm("mma.sync.aligned.m16n8k16.row.col.f32.bf16.bf16.f32 "
        "{%0,%1,%2,%3},{%4,%5,%6,%7},{%8,%9},{%0,%1,%2,%3};"
        : "+f"(c[0]), "+f"(c[1]), "+f"(c[2]), "+f"(c[3])
        : "r"(a0), "r"(a1), "r"(a2), "r"(a3), "r"(b0), "r"(b1));
}
__device__ __forceinline__ uint32_t packbf(float hi, float lo) {
    uint32_t d; asm("cvt.rn.bf16x2.f32 %0, %1, %2;" : "=r"(d) : "f"(hi), "f"(lo));
    return d;
}

__global__ void pack_adj(const int* __restrict__ adj) {
    if (blockIdx.x == 0 && threadIdx.x == 0) { g_ctr[0] = 0; g_ctr[1] = 0; }
    int idx = blockIdx.x * 256 + threadIdx.x;
    int i = idx >> 12, j = idx & 4095;
    unsigned w = __ballot_sync(0xFFFFFFFFu, adj[idx] > 0);
    if ((j & 31) == 0) g_adjbits[(j >> 5) * Nn + i] = w;
}

// C = epi((A[+A2]) @ B + bias)  [C may be null]
// bT != null: also write C^T as bf16, leading dim Nn
// aV != null: fused attention-score epilogue -> rowdat/coldat
__global__ __launch_bounds__(256)
void gemm64(const float* __restrict__ A, const float* __restrict__ A2,
            const float* __restrict__ B, const float* __restrict__ bias,
            float* __restrict__ C, int K, int transB, int doElu,
            __nv_bfloat16* __restrict__ bT,
            const float* __restrict__ aV, float4* __restrict__ rowdat, float4* __restrict__ coldat,
            long Bg, long Cg, long Tg, long Ag)
{
    __shared__ __align__(16) float As[16][68];
    __shared__ __align__(16) float Bs[16][68];
    int gy = blockIdx.y;
    B += (long)gy * Bg;
    if (C)  C  += (long)gy * Cg;
    if (bT) bT += (long)gy * Tg;
    if (aV) { aV += (long)gy * Ag; rowdat += (long)gy * Nn; coldat += (long)gy * Nn; }
    int tid = threadIdx.x, ibase = blockIdx.x * 64;
    int r0 = (tid >> 4) << 2, c0 = (tid & 15) << 2;
    int ai = tid >> 2, akq = tid & 3;
    float acc[4][4] = {};
    for (int k0 = 0; k0 < K; k0 += 16) {
        __syncthreads();
        float4 v = *(const float4*)&A[(size_t)(ibase + ai) * K + k0 + akq * 4];
        if (A2) { float4 u = *(const float4*)&A2[(size_t)(ibase + ai) * K + k0 + akq * 4];
                  v.x += u.x; v.y += u.y; v.z += u.z; v.w += u.w; }
        As[akq*4+0][ai] = v.x; As[akq*4+1][ai] = v.y; As[akq*4+2][ai] = v.z; As[akq*4+3][ai] = v.w;
        if (!transB) {
            int bk = tid >> 4, bf = (tid & 15) << 2;
            *(float4*)&Bs[bk][bf] = *(const float4*)&B[(size_t)(k0 + bk) * 64 + bf];
        } else {
            int bf = tid >> 2, bkq = tid & 3;
            float4 u = *(const float4*)&B[(size_t)bf * K + k0 + bkq * 4];
            Bs[bkq*4+0][bf] = u.x; Bs[bkq*4+1][bf] = u.y; Bs[bkq*4+2][bf] = u.z; Bs[bkq*4+3][bf] = u.w;
        }
        __syncthreads();
        #pragma unroll
        for (int k = 0; k < 16; ++k) {
            float4 a4 = *(const float4*)&As[k][r0];
            float4 b4 = *(const float4*)&Bs[k][c0];
            acc[0][0]+=a4.x*b4.x; acc[0][1]+=a4.x*b4.y; acc[0][2]+=a4.x*b4.z; acc[0][3]+=a4.x*b4.w;
            acc[1][0]+=a4.y*b4.x; acc[1][1]+=a4.y*b4.y; acc[1][2]+=a4.y*b4.z; acc[1][3]+=a4.y*b4.w;
            acc[2][0]+=a4.z*b4.x; acc[2][1]+=a4.z*b4.y; acc[2][2]+=a4.z*b4.z; acc[2][3]+=a4.z*b4.w;
            acc[3][0]+=a4.w*b4.x; acc[3][1]+=a4.w*b4.y; acc[3][2]+=a4.w*b4.z; acc[3][3]+=a4.w*b4.w;
        }
    }
    if (C) {
        float b0 = bias?bias[c0]:0.f, b1 = bias?bias[c0+1]:0.f, b2 = bias?bias[c0+2]:0.f, b3 = bias?bias[c0+3]:0.f;
        #pragma unroll
        for (int r = 0; r < 4; ++r) {
            float4 o = make_float4(acc[r][0]+b0, acc[r][1]+b1, acc[r][2]+b2, acc[r][3]+b3);
            if (doElu) { o.x=eluf(o.x); o.y=eluf(o.y); o.z=eluf(o.z); o.w=eluf(o.w); }
            *(float4*)&C[(size_t)(ibase + r0 + r) * 64 + c0] = o;
        }
    }
    if (bT) {
        #pragma unroll
        for (int c = 0; c < 4; ++c) {
            ushort4 h;
            h.x = __bfloat16_as_ushort(__float2bfloat16_rn(acc[0][c]));
            h.y = __bfloat16_as_ushort(__float2bfloat16_rn(acc[1][c]));
            h.z = __bfloat16_as_ushort(__float2bfloat16_rn(acc[2][c]));
            h.w = __bfloat16_as_ushort(__float2bfloat16_rn(acc[3][c]));
            *(ushort4*)&bT[(size_t)(c0 + c) * Nn + ibase + r0] = h;
        }
    }
    if (aV) {
        float s1[4], s2[4];
        #pragma unroll
        for (int r = 0; r < 4; ++r) {
            s1[r] = acc[r][0]*aV[c0] + acc[r][1]*aV[c0+1] + acc[r][2]*aV[c0+2] + acc[r][3]*aV[c0+3];
            s2[r] = acc[r][0]*aV[64+c0] + acc[r][1]*aV[64+c0+1] + acc[r][2]*aV[64+c0+2] + acc[r][3]*aV[64+c0+3];
            #pragma unroll
            for (int off = 1; off < 16; off <<= 1) {
                s1[r] += __shfl_xor_sync(0xFFFFFFFFu, s1[r], off, 16);
                s2[r] += __shfl_xor_sync(0xFFFFFFFFu, s2[r], off, 16);
            }
        }
        if ((tid & 15) == 0) {
            #pragma unroll
            for (int r = 0; r < 4; ++r) {
                int row = ibase + r0 + r;
                rowdat[row] = make_float4(s1[r], expf(s1[r]), expf(LRALPHA*s1[r]), 0.f);
                coldat[row] = make_float4(s2[r], expf(s2[r]), expf(LRALPHA*s2[r]), 0.f);
            }
        }
    }
}

// masked-softmax aggregation: bf16 m16n8k16 mma.sync.
// 256 threads / 8 warps; each warp owns one m16 row-tile (block = 128 rows).
// TJ=64 per stage; denominator via all-ones B fragment MMA.
__global__ __launch_bounds__(256, 2)
void gat_attn_mma(const __nv_bfloat16* __restrict__ WhB, const float4* __restrict__ rowdat,
                  const float4* __restrict__ coldat, float* __restrict__ part,
                  float* __restrict__ den, int G, int ksplit, int layer)
{
    __shared__ __align__(16) __nv_bfloat16 Bsm[2][64 * 72];
    __shared__ unsigned bitsS[2][2][128];
    __shared__ __align__(16) float4 cdsS[2][64];
    __shared__ int itemS;

    int tid = threadIdx.x, w = tid >> 5, lane = tid & 31;
    int la = lane & 3, lp = lane >> 2;
    uint32_t bsB = smem_u32(&Bsm[0][0]);
    uint32_t btB = smem_u32(&bitsS[0][0][0]);
    uint32_t cdB = smem_u32(&cdsS[0][0]);

    int jchunk = Nn / ksplit, ntiles = jchunk / 64;
    int nItems = 32 * G * ksplit;

    while (true) {
        if (tid == 0) itemS = atomicAdd(&g_ctr[layer], 1);
        __syncthreads();
        int item = itemS;
        if (item >= nItems) break;
        int ib = item & 31, rest = item >> 5;
        int g = rest % G, ks = rest / G;
        int ibase = ib * 128, jbase0 = ks * jchunk;
        int gN = g * Nn;
        const __nv_bfloat16* WhBg = WhB + (size_t)g * 64 * Nn;

        float4 rdv[2];
        #pragma unroll
        for (int h = 0; h < 2; ++h) rdv[h] = rowdat[gN + ibase + w*16 + 8*h + lp];
        float cA[8][4];
        float cD[4] = {0.f, 0.f, 0.f, 0.f};
        #pragma unroll
        for (int n = 0; n < 8; ++n) { cA[n][0]=0.f; cA[n][1]=0.f; cA[n][2]=0.f; cA[n][3]=0.f; }

        auto stage = [&](int jbase, int buf) {
            #pragma unroll
            for (int r = 0; r < 2; ++r) {
                int e = tid + 256 * r;
                int f = e >> 3, ch = e & 7;
                CP16(bsB + (uint32_t)(buf * 9216 + f * 144 + ch * 16),
                     WhBg + (size_t)f * Nn + jbase + ch * 8);
            }
            {
                int word = tid >> 7, row = tid & 127;
                CP4(btB + (uint32_t)((buf*2+word)*512 + row*4),
                    &g_adjbits[((jbase>>5)+word)*Nn + ibase + row]);
            }
            if (tid < 64) CP16(cdB + (uint32_t)(buf*64 + tid)*16, &coldat[gN + jbase + tid]);
            CPCOMMIT();
        };

        stage(jbase0, 0);
        int buf = 0;
        for (int t = 0; t < ntiles; ++t) {
            if (t + 1 < ntiles) stage(jbase0 + (t + 1) * 64, buf ^ 1);
            else CPCOMMIT();
            CPWAIT1();
            __syncthreads();
            unsigned rbw[2][2];
            #pragma unroll
            for (int h = 0; h < 2; ++h) {
                rbw[0][h] = bitsS[buf][0][w*16 + 8*h + lp];
                rbw[1][h] = bitsS[buf][1][w*16 + 8*h + lp];
            }
            const __nv_bfloat16* bbase = &Bsm[buf][0];
            #pragma unroll
            for (int ks2 = 0; ks2 < 4; ++ks2) {
                int jk = ks2 * 16;
                int jl = (jk & 31) + 2*la;
                int wsel = ks2 >> 1;
                float4 c0 = cdsS[buf][jk + 2*la];
                float4 c1 = cdsS[buf][jk + 2*la + 1];
                float4 c2 = cdsS[buf][jk + 2*la + 8];
                float4 c3 = cdsS[buf][jk + 2*la + 9];
                uint32_t Alo[2], Ahi[2];
                #pragma unroll
                for (int h = 0; h < 2; ++h) {
                    unsigned rb = rbw[wsel][h];
                    float rx = rdv[h].x, ry = rdv[h].y, rz = rdv[h].z;
                    float p0 = slctf(ry*c0.y, rz*c0.z, rx + c0.x);
                    float p1 = slctf(ry*c1.y, rz*c1.z, rx + c1.x);
                    float p2 = slctf(ry*c2.y, rz*c2.z, rx + c2.x);
                    float p3 = slctf(ry*c3.y, rz*c3.z, rx + c3.x);
                    float w0 = slcti(0.f, p0, (int)(rb << (31 - jl)));
                    float w1 = slcti(0.f, p1, (int)(rb << (30 - jl)));
                    float w2 = slcti(0.f, p2, (int)(rb << (23 - jl)));
                    float w3 = slcti(0.f, p3, (int)(rb << (22 - jl)));
                    Alo[h] = packbf(w1, w0);
                    Ahi[h] = packbf(w3, w2);
                }
                #pragma unroll
                for (int n = 0; n < 8; ++n) {
                    const __nv_bfloat16* bp = bbase + (n*8 + lp) * 72 + jk + 2*la;
                    uint32_t b0 = *(const uint32_t*)bp;
                    uint32_t b1 = *(const uint32_t*)(bp + 8);
                    mma16(cA[n], Alo[0], Alo[1], Ahi[0], Ahi[1], b0, b1);
                }
                mma16(cD, Alo[0], Alo[1], Ahi[0], Ahi[1], ONES2, ONES2);
            }
            __syncthreads();
            buf ^= 1;
        }
        int p = g * ksplit + ks;
        int r0 = ibase + w*16 + lp;
        if (la == 0) {
            den[(size_t)p * Nn + r0]     = cD[0];
            den[(size_t)p * Nn + r0 + 8] = cD[2];
        }
        #pragma unroll
        for (int n = 0; n < 8; ++n) {
            float* d0 = &part[((size_t)p * Nn + r0) * 64 + n*8 + 2*la];
            *(float2*)d0 = make_float2(cA[n][0], cA[n][1]);
            *(float2*)(d0 + 8 * 64) = make_float2(cA[n][2], cA[n][3]);
        }
    }
}

__global__ void combine(const float* __restrict__ part, const float* __restrict__ den,
                        float* __restrict__ dst, int G, int ksplit, int dstStride)
{
    int idx = blockIdx.x * 256 + threadIdx.x;
    int f = idx & 63;
    int g = (idx >> 6) % G;
    int i = idx / (64 * G);
    float s = 0.f, d = 0.f;
    for (int ks = 0; ks < ksplit; ++ks) {
        int p = g * ksplit + ks;
        s += part[((size_t)p * Nn + i) * 64 + f];
        d += den[(size_t)p * Nn + i];
    }
    dst[(size_t)i * dstStride + g * 64 + f] = eluf(s / d);
}

extern "C" void kernel_launch(void* const* d_in, const int* in_sizes, int n_in,
                              void* d_out, int out_size)
{
    const float* x        = (const float*)d_in[0];
    const int*   adj      = (const int*)d_in[1];
    const float* w_heads  = (const float*)d_in[2];
    const float* a_heads  = (const float*)d_in[3];
    const float* w_out    = (const float*)d_in[4];
    const float* a_out    = (const float*)d_in[5];
    const float* lin_w    = (const float*)d_in[6];
    const float* lin_b    = (const float*)d_in[7];
    const float* outlin_w = (const float*)d_in[8];
    const float* outlin_b = (const float*)d_in[9];
    float* out = (float*)d_out;

    float *pHcat, *pXres, *pAtt2, *pPart, *pDen;
    __nv_bfloat16 *pWhB, *pWh2B;
    float4 *pRow, *pCol;
    cudaGetSymbolAddress((void**)&pWhB,  g_WhB);
    cudaGetSymbolAddress((void**)&pWh2B, g_Wh2B);
    cudaGetSymbolAddress((void**)&pHcat, g_hcat);
    cudaGetSymbolAddress((void**)&pXres, g_xres);
    cudaGetSymbolAddress((void**)&pAtt2, g_att2);
    cudaGetSymbolAddress((void**)&pPart, g_part);
    cudaGetSymbolAddress((void**)&pDen,  g_den);
    cudaGetSymbolAddress((void**)&pRow,  g_rowdat);
    cudaGetSymbolAddress((void**)&pCol,  g_coldat);

    pack_adj<<<(Nn * Nn) / 256, 256>>>(adj);
    // layer-1: Wh per head -> bf16 transposed + fused scores (no fp32 Wh)
    gemm64<<<dim3(Nn/64, 4), 256>>>(x, nullptr, w_heads, nullptr, nullptr, 128, 0, 0,
                                    pWhB, a_heads, pRow, pCol,
                                    128L*64, 0, 64L*Nn, 128);
    gemm64<<<dim3(Nn/64, 1), 256>>>(x, nullptr, lin_w, lin_b, pXres, 128, 1, 0,
                                    nullptr, nullptr, nullptr, nullptr, 0, 0, 0, 0);
    gat_attn_mma<<<296, 256>>>(pWhB, pRow, pCol, pPart, pDen, 4, 2, 0);
    combine<<<(Nn * 4 * 64) / 256, 256>>>(pPart, pDen, pHcat, 4, 2, 256);
    // layer-2: Wh2 -> bf16 transposed + fused scores
    gemm64<<<dim3(Nn/64, 1), 256>>>(pHcat, nullptr, w_out, nullptr, nullptr, 256, 0, 0,
                                    pWh2B, a_out, pRow, pCol, 0, 0, 0, 0);
    gat_attn_mma<<<296, 256>>>(pWh2B, pRow, pCol, pPart, pDen, 1, 8, 1);
    combine<<<(Nn * 64) / 256, 256>>>(pPart, pDen, pAtt2, 1, 8, 64);
    gemm64<<<dim3(Nn/64, 1), 256>>>(pXres, pAtt2, outlin_w, outlin_b, out, 64, 1, 1,
                                    nullptr, nullptr, nullptr, nullptr, 0, 0, 0, 0);
}